// round 1
// baseline (speedup 1.0000x reference)
#include <cuda_runtime.h>
#include <cstdint>
#include <cstddef>

// Problem constants
constexpr int kB   = 2;
constexpr int kS   = 2048;
constexpr int kD   = 1024;
constexpr int kHID = 1024;
constexpr int kH   = 16;
constexpr int kHD  = 64;           // head dim
constexpr int kM   = kB * kS;      // 4096 rows
constexpr float kScale = 0.03125f; // 1/sqrt(1024)

// Scratch buffers (allocation-free rule: __device__ globals)
__device__ float g_q[(size_t)kM * kHID];
__device__ float g_k[(size_t)kM * kHID];
__device__ float g_v[(size_t)kM * kHID];
__device__ float g_ctx[(size_t)kM * kHID];

// ---------------------------------------------------------------------------
// SGEMM: C[M,N] = A[M,K] @ W[N,K]^T + bias[N]
// BM=BN=128, BK=8, 256 threads, 8x8 microtile per thread.
// ---------------------------------------------------------------------------
__global__ __launch_bounds__(256, 1) void sgemm_tn_bias(
    const float* __restrict__ A, const float* __restrict__ W,
    const float* __restrict__ bias, float* __restrict__ C,
    int M, int N, int K)
{
    constexpr int BK = 8;
    constexpr int PAD = 132; // 128 + 4 to kill store bank conflicts
    __shared__ float As[BK * PAD];
    __shared__ float Ws[BK * PAD];

    const int tid  = threadIdx.x;
    const int brow = blockIdx.y * 128;
    const int bcol = blockIdx.x * 128;
    const int tr   = (tid >> 4) * 8;  // row offset of microtile
    const int tc   = (tid & 15) * 8;  // col offset of microtile
    const int lr   = tid >> 1;        // load row 0..127
    const int lc   = (tid & 1) * 4;   // load col 0 or 4

    const float* Ag = A + (size_t)(brow + lr) * K + lc;
    const float* Wg = W + (size_t)(bcol + lr) * K + lc;

    float acc[8][8];
    #pragma unroll
    for (int i = 0; i < 8; i++)
        #pragma unroll
        for (int j = 0; j < 8; j++) acc[i][j] = 0.f;

    for (int k0 = 0; k0 < K; k0 += BK) {
        float4 av = *(const float4*)(Ag + k0);
        float4 wv = *(const float4*)(Wg + k0);
        As[(lc + 0) * PAD + lr] = av.x;
        As[(lc + 1) * PAD + lr] = av.y;
        As[(lc + 2) * PAD + lr] = av.z;
        As[(lc + 3) * PAD + lr] = av.w;
        Ws[(lc + 0) * PAD + lr] = wv.x;
        Ws[(lc + 1) * PAD + lr] = wv.y;
        Ws[(lc + 2) * PAD + lr] = wv.z;
        Ws[(lc + 3) * PAD + lr] = wv.w;
        __syncthreads();

        #pragma unroll
        for (int kk = 0; kk < BK; kk++) {
            float ra[8], rb[8];
            *(float4*)&ra[0] = *(const float4*)&As[kk * PAD + tr];
            *(float4*)&ra[4] = *(const float4*)&As[kk * PAD + tr + 4];
            *(float4*)&rb[0] = *(const float4*)&Ws[kk * PAD + tc];
            *(float4*)&rb[4] = *(const float4*)&Ws[kk * PAD + tc + 4];
            #pragma unroll
            for (int i = 0; i < 8; i++)
                #pragma unroll
                for (int j = 0; j < 8; j++)
                    acc[i][j] += ra[i] * rb[j];
        }
        __syncthreads();
    }

    float rbias[8];
    #pragma unroll
    for (int j = 0; j < 8; j++) rbias[j] = bias[bcol + tc + j];

    #pragma unroll
    for (int i = 0; i < 8; i++) {
        float4 o0, o1;
        o0.x = acc[i][0] + rbias[0]; o0.y = acc[i][1] + rbias[1];
        o0.z = acc[i][2] + rbias[2]; o0.w = acc[i][3] + rbias[3];
        o1.x = acc[i][4] + rbias[4]; o1.y = acc[i][5] + rbias[5];
        o1.z = acc[i][6] + rbias[6]; o1.w = acc[i][7] + rbias[7];
        float* cp = C + (size_t)(brow + tr + i) * N + bcol + tc;
        *(float4*)(cp)     = o0;
        *(float4*)(cp + 4) = o1;
    }
}

// ---------------------------------------------------------------------------
// Fused attention: per block = one (b,h) and 128 queries. Streams K/V in
// 128-row tiles; online softmax; output written to ctx in [M, HID] layout.
// ---------------------------------------------------------------------------
constexpr int QT = 128;
constexpr int KT = 128;
constexpr int SPAD = 132; // stride for Qs/Ks/Ss
constexpr int VPAD = 68;  // stride for Vs
// floats: Qs 64*132 + Ks 64*132 + Ss 128*132 + Vs 128*68 + rowL/rowC 256
constexpr int ATTN_SMEM_FLOATS = kHD * SPAD * 2 + KT * SPAD + KT * VPAD + 2 * QT;
constexpr int ATTN_SMEM_BYTES  = ATTN_SMEM_FLOATS * 4; // 171,008 B

__global__ __launch_bounds__(256, 1) void attn_kernel(
    const float* __restrict__ Q, const float* __restrict__ Km,
    const float* __restrict__ Vm, float* __restrict__ O)
{
    extern __shared__ float sm[];
    float* Qs   = sm;                    // [64][SPAD]   d-major: Qs[d][i]
    float* Ks   = Qs + kHD * SPAD;       // [64][SPAD]   Ks[d][j]
    float* Ssm  = Ks + kHD * SPAD;       // [128][SPAD]  Ssm[j][i]
    float* Vs   = Ssm + KT * SPAD;       // [128][VPAD]  Vs[j][d]
    float* rowL = Vs + KT * VPAD;        // [128]
    float* rowC = rowL + QT;             // [128]

    const int tid = threadIdx.x;
    const int bh  = blockIdx.y;
    const int b   = bh >> 4;   // / kH
    const int h   = bh & 15;
    const int q0  = blockIdx.x * QT;

    const float* Qg = Q + ((size_t)(b * kS + q0)) * kHID + h * kHD;

    // load Q tile (scaled by 1/sqrt(HID)), transposed to d-major
    for (int idx = tid; idx < QT * (kHD / 4); idx += 256) {
        int i  = idx >> 4;
        int dv = (idx & 15) << 2;
        float4 t = *(const float4*)(Qg + (size_t)i * kHID + dv);
        Qs[(dv + 0) * SPAD + i] = t.x * kScale;
        Qs[(dv + 1) * SPAD + i] = t.y * kScale;
        Qs[(dv + 2) * SPAD + i] = t.z * kScale;
        Qs[(dv + 3) * SPAD + i] = t.w * kScale;
    }
    if (tid < QT) rowL[tid] = 0.f;
    float m_i = -1e30f;

    const int ti = (tid & 15) * 8;  // 8 query rows owned for S and PV
    const int tj = (tid >> 4) * 8;  // 8 key cols for S microtile
    const int td = (tid >> 4) * 4;  // 4 head dims for PV microtile

    float acc[8][4];
    #pragma unroll
    for (int i = 0; i < 8; i++)
        #pragma unroll
        for (int d = 0; d < 4; d++) acc[i][d] = 0.f;

    __syncthreads();

    for (int kt = 0; kt < kS; kt += KT) {
        const float* Kg = Km + ((size_t)(b * kS + kt)) * kHID + h * kHD;
        const float* Vg = Vm + ((size_t)(b * kS + kt)) * kHID + h * kHD;

        // load K (transposed) and V (direct)
        for (int idx = tid; idx < KT * (kHD / 4); idx += 256) {
            int j  = idx >> 4;
            int dv = (idx & 15) << 2;
            float4 tk = *(const float4*)(Kg + (size_t)j * kHID + dv);
            Ks[(dv + 0) * SPAD + j] = tk.x;
            Ks[(dv + 1) * SPAD + j] = tk.y;
            Ks[(dv + 2) * SPAD + j] = tk.z;
            Ks[(dv + 3) * SPAD + j] = tk.w;
            float4 tv = *(const float4*)(Vg + (size_t)j * kHID + dv);
            *(float4*)&Vs[j * VPAD + dv] = tv;
        }
        __syncthreads();

        // S[j][i] = sum_d Q[i][d]*K[j][d] (Q pre-scaled)
        float sreg[8][8];
        #pragma unroll
        for (int jj = 0; jj < 8; jj++)
            #pragma unroll
            for (int ii = 0; ii < 8; ii++) sreg[jj][ii] = 0.f;

        #pragma unroll 8
        for (int d = 0; d < kHD; d++) {
            float ra[8], rb[8];
            *(float4*)&ra[0] = *(const float4*)&Qs[d * SPAD + ti];
            *(float4*)&ra[4] = *(const float4*)&Qs[d * SPAD + ti + 4];
            *(float4*)&rb[0] = *(const float4*)&Ks[d * SPAD + tj];
            *(float4*)&rb[4] = *(const float4*)&Ks[d * SPAD + tj + 4];
            #pragma unroll
            for (int jj = 0; jj < 8; jj++)
                #pragma unroll
                for (int ii = 0; ii < 8; ii++)
                    sreg[jj][ii] += rb[jj] * ra[ii];
        }
        #pragma unroll
        for (int jj = 0; jj < 8; jj++) {
            *(float4*)&Ssm[(tj + jj) * SPAD + ti] =
                make_float4(sreg[jj][0], sreg[jj][1], sreg[jj][2], sreg[jj][3]);
            *(float4*)&Ssm[(tj + jj) * SPAD + ti + 4] =
                make_float4(sreg[jj][4], sreg[jj][5], sreg[jj][6], sreg[jj][7]);
        }
        __syncthreads();

        // online softmax per row (threads 0..127)
        if (tid < QT) {
            float t0 = -1e30f, t1 = -1e30f, t2 = -1e30f, t3 = -1e30f;
            #pragma unroll 4
            for (int j = 0; j < KT; j += 4) {
                t0 = fmaxf(t0, Ssm[(j + 0) * SPAD + tid]);
                t1 = fmaxf(t1, Ssm[(j + 1) * SPAD + tid]);
                t2 = fmaxf(t2, Ssm[(j + 2) * SPAD + tid]);
                t3 = fmaxf(t3, Ssm[(j + 3) * SPAD + tid]);
            }
            float tm   = fmaxf(fmaxf(t0, t1), fmaxf(t2, t3));
            float mnew = fmaxf(m_i, tm);
            float corr = __expf(m_i - mnew);
            float s0 = 0.f, s1 = 0.f, s2 = 0.f, s3 = 0.f;
            #pragma unroll 4
            for (int j = 0; j < KT; j += 4) {
                float p0 = __expf(Ssm[(j + 0) * SPAD + tid] - mnew);
                float p1 = __expf(Ssm[(j + 1) * SPAD + tid] - mnew);
                float p2 = __expf(Ssm[(j + 2) * SPAD + tid] - mnew);
                float p3 = __expf(Ssm[(j + 3) * SPAD + tid] - mnew);
                Ssm[(j + 0) * SPAD + tid] = p0;
                Ssm[(j + 1) * SPAD + tid] = p1;
                Ssm[(j + 2) * SPAD + tid] = p2;
                Ssm[(j + 3) * SPAD + tid] = p3;
                s0 += p0; s1 += p1; s2 += p2; s3 += p3;
            }
            rowL[tid] = rowL[tid] * corr + ((s0 + s1) + (s2 + s3));
            rowC[tid] = corr;
            m_i = mnew;
        }
        __syncthreads();

        // rescale accumulators, then acc += P @ V
        float cr[8];
        #pragma unroll
        for (int ii = 0; ii < 8; ii++) cr[ii] = rowC[ti + ii];
        #pragma unroll
        for (int ii = 0; ii < 8; ii++)
            #pragma unroll
            for (int dd = 0; dd < 4; dd++) acc[ii][dd] *= cr[ii];

        #pragma unroll 4
        for (int j = 0; j < KT; j++) {
            float rp[8], rv[4];
            *(float4*)&rp[0] = *(const float4*)&Ssm[j * SPAD + ti];
            *(float4*)&rp[4] = *(const float4*)&Ssm[j * SPAD + ti + 4];
            *(float4*)&rv[0] = *(const float4*)&Vs[j * VPAD + td];
            #pragma unroll
            for (int ii = 0; ii < 8; ii++)
                #pragma unroll
                for (int dd = 0; dd < 4; dd++)
                    acc[ii][dd] += rp[ii] * rv[dd];
        }
        __syncthreads();
    }

    // normalize and write out to ctx[M, HID] layout
    float li[8];
    #pragma unroll
    for (int ii = 0; ii < 8; ii++) li[ii] = 1.f / rowL[ti + ii];

    float* Og = O + ((size_t)(b * kS + q0)) * kHID + h * kHD;
    #pragma unroll
    for (int ii = 0; ii < 8; ii++) {
        float4 o;
        o.x = acc[ii][0] * li[ii];
        o.y = acc[ii][1] * li[ii];
        o.z = acc[ii][2] * li[ii];
        o.w = acc[ii][3] * li[ii];
        *(float4*)(Og + (size_t)(ti + ii) * kHID + td) = o;
    }
}

// ---------------------------------------------------------------------------
// launch
// ---------------------------------------------------------------------------
extern "C" void kernel_launch(void* const* d_in, const int* in_sizes, int n_in,
                              void* d_out, int out_size)
{
    const float* x  = (const float*)d_in[0];
    const float* Wq = (const float*)d_in[1];
    const float* bq = (const float*)d_in[2];
    const float* Wk = (const float*)d_in[3];
    const float* bk = (const float*)d_in[4];
    const float* Wv = (const float*)d_in[5];
    const float* bv = (const float*)d_in[6];
    const float* Wo = (const float*)d_in[7];
    const float* bo = (const float*)d_in[8];
    float* out = (float*)d_out;

    float *q, *k, *v, *ctx;
    cudaGetSymbolAddress((void**)&q,   g_q);
    cudaGetSymbolAddress((void**)&k,   g_k);
    cudaGetSymbolAddress((void**)&v,   g_v);
    cudaGetSymbolAddress((void**)&ctx, g_ctx);

    cudaFuncSetAttribute(attn_kernel,
                         cudaFuncAttributeMaxDynamicSharedMemorySize,
                         ATTN_SMEM_BYTES);

    dim3 gqkv(kHID / 128, kM / 128); // (8, 32)
    sgemm_tn_bias<<<gqkv, 256>>>(x, Wq, bq, q, kM, kHID, kD);
    sgemm_tn_bias<<<gqkv, 256>>>(x, Wk, bk, k, kM, kHID, kD);
    sgemm_tn_bias<<<gqkv, 256>>>(x, Wv, bv, v, kM, kHID, kD);

    dim3 ga(kS / QT, kB * kH);       // (16, 32)
    attn_kernel<<<ga, 256, ATTN_SMEM_BYTES>>>(q, k, v, ctx);

    dim3 go(kD / 128, kM / 128);     // (8, 32)
    sgemm_tn_bias<<<go, 256>>>(ctx, Wo, bo, out, kM, kD, kHID);
}

// round 3
// speedup vs baseline: 1.1448x; 1.1448x over previous
#include <cuda_runtime.h>
#include <cstdint>
#include <cstddef>

// ===========================================================================
// Problem constants
// ===========================================================================
constexpr int kB   = 2;
constexpr int kS   = 2048;
constexpr int kD   = 1024;
constexpr int kHID = 1024;
constexpr int kH   = 16;
constexpr int kHD  = 64;           // head dim
constexpr int kM   = kB * kS;      // 4096 rows
constexpr float kScale = 0.03125f; // 1/sqrt(1024)

// Scratch buffers (allocation-free rule: __device__ globals)
__device__ float g_q[(size_t)kM * kHID];
__device__ float g_k[(size_t)kM * kHID];
__device__ float g_v[(size_t)kM * kHID];
__device__ float g_ctx[(size_t)kM * kHID];

// ===========================================================================
// tf32 mma.sync helpers (sm_80+ — no arch-accelerated "a" features needed)
// ===========================================================================
__device__ __forceinline__ uint32_t cvt_tf32(float x) {
    uint32_t r;
    asm("cvt.rna.tf32.f32 %0, %1;" : "=r"(r) : "f"(x));
    return r;
}

__device__ __forceinline__ void split_tf32(float x, uint32_t& h, uint32_t& l) {
    h = cvt_tf32(x);
    l = cvt_tf32(x - __uint_as_float(h));
}

__device__ __forceinline__ void mma_tf32(float* d, const uint32_t* a, const uint32_t* b) {
    asm volatile(
        "mma.sync.aligned.m16n8k8.row.col.f32.tf32.tf32.f32 "
        "{%0,%1,%2,%3}, {%4,%5,%6,%7}, {%8,%9}, {%0,%1,%2,%3};"
        : "+f"(d[0]), "+f"(d[1]), "+f"(d[2]), "+f"(d[3])
        : "r"(a[0]), "r"(a[1]), "r"(a[2]), "r"(a[3]),
          "r"(b[0]), "r"(b[1]));
}

// ===========================================================================
// 3xTF32 GEMM via mma.sync: C[M,N] = A[M,K] @ W[N,K]^T + bias[N]
// CTA tile 128x128, BK=32, 8 warps (4 row x 2 col), warp tile 32x64.
// smem holds fp32 tiles in [m][k] layout (stride 36); hi/lo tf32 split
// happens at fragment-load time. Double-buffered smem + register prefetch.
// ===========================================================================
constexpr int GBK   = 32;
constexpr int KSTR  = 36;               // k-stride (32 + 4 pad)
constexpr int TSZ   = 128 * KSTR;       // floats per operand tile (4608)
constexpr int BUFSZ = 2 * TSZ;          // A + B per stage (9216 floats)
constexpr int GEMM_SMEM_BYTES = 2 * BUFSZ * 4;  // 73728 B

__global__ __launch_bounds__(256, 1)
void gemm_mma_tf32x3(const float* __restrict__ A, const float* __restrict__ W,
                     const float* __restrict__ bias, float* __restrict__ C,
                     int M, int N, int K)
{
    extern __shared__ float smf[];

    const int tid  = threadIdx.x;
    const int wid  = tid >> 5;
    const int lane = tid & 31;
    const int g    = lane >> 2;   // groupID (0..7)
    const int t    = lane & 3;    // thread-in-group (0..3)

    const int wm = (wid & 3) * 32;   // warp row offset in CTA tile
    const int wn = (wid >> 2) * 64;  // warp col offset in CTA tile

    const int brow = blockIdx.y * 128;
    const int bcol = blockIdx.x * 128;
    const int nchunks = K / GBK;

    // gmem load mapping: float4 index f = i*256 + tid; r = f>>3, s = f&7
    const int lr = tid >> 3;        // base row (0..31), +32*i
    const int ls = (tid & 7) * 4;   // col within chunk (0,4,..28)

    const float* Ag = A + (size_t)brow * K + ls;
    const float* Wg = W + (size_t)bcol * K + ls;

    float acc[2][8][4];
    #pragma unroll
    for (int mi = 0; mi < 2; mi++)
        #pragma unroll
        for (int nf = 0; nf < 8; nf++)
            #pragma unroll
            for (int j = 0; j < 4; j++) acc[mi][nf][j] = 0.f;

    float4 pa[4], pb[4];

    // prologue: load chunk 0 and stage into buffer 0
    #pragma unroll
    for (int i = 0; i < 4; i++) {
        pa[i] = *(const float4*)(Ag + (size_t)(lr + 32 * i) * K);
        pb[i] = *(const float4*)(Wg + (size_t)(lr + 32 * i) * K);
    }
    #pragma unroll
    for (int i = 0; i < 4; i++) {
        *(float4*)(smf + (lr + 32 * i) * KSTR + ls)       = pa[i];
        *(float4*)(smf + TSZ + (lr + 32 * i) * KSTR + ls) = pb[i];
    }
    __syncthreads();

    for (int c = 0; c < nchunks; c++) {
        // prefetch next chunk into registers
        if (c + 1 < nchunks) {
            const float* Agn = Ag + (size_t)(c + 1) * GBK;
            const float* Wgn = Wg + (size_t)(c + 1) * GBK;
            #pragma unroll
            for (int i = 0; i < 4; i++) {
                pa[i] = *(const float4*)(Agn + (size_t)(lr + 32 * i) * K);
                pb[i] = *(const float4*)(Wgn + (size_t)(lr + 32 * i) * K);
            }
        }

        const float* As = smf + (c & 1) * BUFSZ;
        const float* Bs = As + TSZ;

        // compute: 4 k-steps of m16n8k8, 3xTF32
        #pragma unroll
        for (int kk = 0; kk < 4; kk++) {
            const int k0 = kk * 8;
            uint32_t aH[2][4], aL[2][4];
            #pragma unroll
            for (int mi = 0; mi < 2; mi++) {
                const int m0 = wm + mi * 16;
                float f0 = As[(m0 + g)     * KSTR + k0 + t];
                float f1 = As[(m0 + g + 8) * KSTR + k0 + t];
                float f2 = As[(m0 + g)     * KSTR + k0 + t + 4];
                float f3 = As[(m0 + g + 8) * KSTR + k0 + t + 4];
                split_tf32(f0, aH[mi][0], aL[mi][0]);
                split_tf32(f1, aH[mi][1], aL[mi][1]);
                split_tf32(f2, aH[mi][2], aL[mi][2]);
                split_tf32(f3, aH[mi][3], aL[mi][3]);
            }
            #pragma unroll
            for (int nf = 0; nf < 8; nf++) {
                const int n0 = wn + nf * 8 + g;
                float b0 = Bs[n0 * KSTR + k0 + t];
                float b1 = Bs[n0 * KSTR + k0 + t + 4];
                uint32_t bH[2], bL[2];
                split_tf32(b0, bH[0], bL[0]);
                split_tf32(b1, bH[1], bL[1]);
                #pragma unroll
                for (int mi = 0; mi < 2; mi++) {
                    mma_tf32(acc[mi][nf], aH[mi], bH);
                    mma_tf32(acc[mi][nf], aL[mi], bH);
                    mma_tf32(acc[mi][nf], aH[mi], bL);
                }
            }
        }

        // stage next chunk into the other buffer
        if (c + 1 < nchunks) {
            float* Ad = smf + ((c + 1) & 1) * BUFSZ;
            float* Bd = Ad + TSZ;
            #pragma unroll
            for (int i = 0; i < 4; i++) {
                *(float4*)(Ad + (lr + 32 * i) * KSTR + ls) = pa[i];
                *(float4*)(Bd + (lr + 32 * i) * KSTR + ls) = pb[i];
            }
        }
        __syncthreads();
    }

    // epilogue: add bias, store
    #pragma unroll
    for (int mi = 0; mi < 2; mi++) {
        const int r0 = brow + wm + mi * 16 + g;
        #pragma unroll
        for (int nf = 0; nf < 8; nf++) {
            const int c0 = bcol + wn + nf * 8 + 2 * t;
            float2 bi = *(const float2*)(bias + c0);
            float2 v0, v1;
            v0.x = acc[mi][nf][0] + bi.x;
            v0.y = acc[mi][nf][1] + bi.y;
            v1.x = acc[mi][nf][2] + bi.x;
            v1.y = acc[mi][nf][3] + bi.y;
            *(float2*)(C + (size_t)r0 * N + c0)       = v0;
            *(float2*)(C + (size_t)(r0 + 8) * N + c0) = v1;
        }
    }
}

// ===========================================================================
// Fused attention (unchanged fp32 baseline): per block = one (b,h), 128 queries.
// ===========================================================================
constexpr int QT = 128;
constexpr int KT = 128;
constexpr int SPAD = 132;
constexpr int VPAD = 68;
constexpr int ATTN_SMEM_FLOATS = kHD * SPAD * 2 + KT * SPAD + KT * VPAD + 2 * QT;
constexpr int ATTN_SMEM_BYTES  = ATTN_SMEM_FLOATS * 4;

__global__ __launch_bounds__(256, 1) void attn_kernel(
    const float* __restrict__ Q, const float* __restrict__ Km,
    const float* __restrict__ Vm, float* __restrict__ O)
{
    extern __shared__ float sm[];
    float* Qs   = sm;
    float* Ks   = Qs + kHD * SPAD;
    float* Ssm  = Ks + kHD * SPAD;
    float* Vs   = Ssm + KT * SPAD;
    float* rowL = Vs + KT * VPAD;
    float* rowC = rowL + QT;

    const int tid = threadIdx.x;
    const int bh  = blockIdx.y;
    const int b   = bh >> 4;
    const int h   = bh & 15;
    const int q0  = blockIdx.x * QT;

    const float* Qg = Q + ((size_t)(b * kS + q0)) * kHID + h * kHD;

    for (int idx = tid; idx < QT * (kHD / 4); idx += 256) {
        int i  = idx >> 4;
        int dv = (idx & 15) << 2;
        float4 tq = *(const float4*)(Qg + (size_t)i * kHID + dv);
        Qs[(dv + 0) * SPAD + i] = tq.x * kScale;
        Qs[(dv + 1) * SPAD + i] = tq.y * kScale;
        Qs[(dv + 2) * SPAD + i] = tq.z * kScale;
        Qs[(dv + 3) * SPAD + i] = tq.w * kScale;
    }
    if (tid < QT) rowL[tid] = 0.f;
    float m_i = -1e30f;

    const int ti = (tid & 15) * 8;
    const int tj = (tid >> 4) * 8;
    const int td = (tid >> 4) * 4;

    float acc[8][4];
    #pragma unroll
    for (int i = 0; i < 8; i++)
        #pragma unroll
        for (int d = 0; d < 4; d++) acc[i][d] = 0.f;

    __syncthreads();

    for (int kt = 0; kt < kS; kt += KT) {
        const float* Kg = Km + ((size_t)(b * kS + kt)) * kHID + h * kHD;
        const float* Vg = Vm + ((size_t)(b * kS + kt)) * kHID + h * kHD;

        for (int idx = tid; idx < KT * (kHD / 4); idx += 256) {
            int j  = idx >> 4;
            int dv = (idx & 15) << 2;
            float4 tk = *(const float4*)(Kg + (size_t)j * kHID + dv);
            Ks[(dv + 0) * SPAD + j] = tk.x;
            Ks[(dv + 1) * SPAD + j] = tk.y;
            Ks[(dv + 2) * SPAD + j] = tk.z;
            Ks[(dv + 3) * SPAD + j] = tk.w;
            float4 tv = *(const float4*)(Vg + (size_t)j * kHID + dv);
            *(float4*)&Vs[j * VPAD + dv] = tv;
        }
        __syncthreads();

        float sreg[8][8];
        #pragma unroll
        for (int jj = 0; jj < 8; jj++)
            #pragma unroll
            for (int ii = 0; ii < 8; ii++) sreg[jj][ii] = 0.f;

        #pragma unroll 8
        for (int d = 0; d < kHD; d++) {
            float ra[8], rb[8];
            *(float4*)&ra[0] = *(const float4*)&Qs[d * SPAD + ti];
            *(float4*)&ra[4] = *(const float4*)&Qs[d * SPAD + ti + 4];
            *(float4*)&rb[0] = *(const float4*)&Ks[d * SPAD + tj];
            *(float4*)&rb[4] = *(const float4*)&Ks[d * SPAD + tj + 4];
            #pragma unroll
            for (int jj = 0; jj < 8; jj++)
                #pragma unroll
                for (int ii = 0; ii < 8; ii++)
                    sreg[jj][ii] += rb[jj] * ra[ii];
        }
        #pragma unroll
        for (int jj = 0; jj < 8; jj++) {
            *(float4*)&Ssm[(tj + jj) * SPAD + ti] =
                make_float4(sreg[jj][0], sreg[jj][1], sreg[jj][2], sreg[jj][3]);
            *(float4*)&Ssm[(tj + jj) * SPAD + ti + 4] =
                make_float4(sreg[jj][4], sreg[jj][5], sreg[jj][6], sreg[jj][7]);
        }
        __syncthreads();

        if (tid < QT) {
            float t0 = -1e30f, t1 = -1e30f, t2 = -1e30f, t3 = -1e30f;
            #pragma unroll 4
            for (int j = 0; j < KT; j += 4) {
                t0 = fmaxf(t0, Ssm[(j + 0) * SPAD + tid]);
                t1 = fmaxf(t1, Ssm[(j + 1) * SPAD + tid]);
                t2 = fmaxf(t2, Ssm[(j + 2) * SPAD + tid]);
                t3 = fmaxf(t3, Ssm[(j + 3) * SPAD + tid]);
            }
            float tm   = fmaxf(fmaxf(t0, t1), fmaxf(t2, t3));
            float mnew = fmaxf(m_i, tm);
            float corr = __expf(m_i - mnew);
            float s0 = 0.f, s1 = 0.f, s2 = 0.f, s3 = 0.f;
            #pragma unroll 4
            for (int j = 0; j < KT; j += 4) {
                float p0 = __expf(Ssm[(j + 0) * SPAD + tid] - mnew);
                float p1 = __expf(Ssm[(j + 1) * SPAD + tid] - mnew);
                float p2 = __expf(Ssm[(j + 2) * SPAD + tid] - mnew);
                float p3 = __expf(Ssm[(j + 3) * SPAD + tid] - mnew);
                Ssm[(j + 0) * SPAD + tid] = p0;
                Ssm[(j + 1) * SPAD + tid] = p1;
                Ssm[(j + 2) * SPAD + tid] = p2;
                Ssm[(j + 3) * SPAD + tid] = p3;
                s0 += p0; s1 += p1; s2 += p2; s3 += p3;
            }
            rowL[tid] = rowL[tid] * corr + ((s0 + s1) + (s2 + s3));
            rowC[tid] = corr;
            m_i = mnew;
        }
        __syncthreads();

        float cr[8];
        #pragma unroll
        for (int ii = 0; ii < 8; ii++) cr[ii] = rowC[ti + ii];
        #pragma unroll
        for (int ii = 0; ii < 8; ii++)
            #pragma unroll
            for (int dd = 0; dd < 4; dd++) acc[ii][dd] *= cr[ii];

        #pragma unroll 4
        for (int j = 0; j < KT; j++) {
            float rp[8], rv[4];
            *(float4*)&rp[0] = *(const float4*)&Ssm[j * SPAD + ti];
            *(float4*)&rp[4] = *(const float4*)&Ssm[j * SPAD + ti + 4];
            *(float4*)&rv[0] = *(const float4*)&Vs[j * VPAD + td];
            #pragma unroll
            for (int ii = 0; ii < 8; ii++)
                #pragma unroll
                for (int dd = 0; dd < 4; dd++)
                    acc[ii][dd] += rp[ii] * rv[dd];
        }
        __syncthreads();
    }

    float li[8];
    #pragma unroll
    for (int ii = 0; ii < 8; ii++) li[ii] = 1.f / rowL[ti + ii];

    float* Og = O + ((size_t)(b * kS + q0)) * kHID + h * kHD;
    #pragma unroll
    for (int ii = 0; ii < 8; ii++) {
        float4 o;
        o.x = acc[ii][0] * li[ii];
        o.y = acc[ii][1] * li[ii];
        o.z = acc[ii][2] * li[ii];
        o.w = acc[ii][3] * li[ii];
        *(float4*)(Og + (size_t)(ti + ii) * kHID + td) = o;
    }
}

// ===========================================================================
// launch
// ===========================================================================
extern "C" void kernel_launch(void* const* d_in, const int* in_sizes, int n_in,
                              void* d_out, int out_size)
{
    const float* x  = (const float*)d_in[0];
    const float* Wq = (const float*)d_in[1];
    const float* bq = (const float*)d_in[2];
    const float* Wk = (const float*)d_in[3];
    const float* bk = (const float*)d_in[4];
    const float* Wv = (const float*)d_in[5];
    const float* bv = (const float*)d_in[6];
    const float* Wo = (const float*)d_in[7];
    const float* bo = (const float*)d_in[8];
    float* out = (float*)d_out;

    float *q, *k, *v, *ctx;
    cudaGetSymbolAddress((void**)&q,   g_q);
    cudaGetSymbolAddress((void**)&k,   g_k);
    cudaGetSymbolAddress((void**)&v,   g_v);
    cudaGetSymbolAddress((void**)&ctx, g_ctx);

    cudaFuncSetAttribute(gemm_mma_tf32x3,
                         cudaFuncAttributeMaxDynamicSharedMemorySize,
                         GEMM_SMEM_BYTES);
    cudaFuncSetAttribute(attn_kernel,
                         cudaFuncAttributeMaxDynamicSharedMemorySize,
                         ATTN_SMEM_BYTES);

    dim3 gqkv(kHID / 128, kM / 128); // (8, 32)
    gemm_mma_tf32x3<<<gqkv, 256, GEMM_SMEM_BYTES>>>(x, Wq, bq, q, kM, kHID, kD);
    gemm_mma_tf32x3<<<gqkv, 256, GEMM_SMEM_BYTES>>>(x, Wk, bk, k, kM, kHID, kD);
    gemm_mma_tf32x3<<<gqkv, 256, GEMM_SMEM_BYTES>>>(x, Wv, bv, v, kM, kHID, kD);

    dim3 ga(kS / QT, kB * kH);       // (16, 32)
    attn_kernel<<<ga, 256, ATTN_SMEM_BYTES>>>(q, k, v, ctx);

    dim3 go(kD / 128, kM / 128);     // (8, 32)
    gemm_mma_tf32x3<<<go, 256, GEMM_SMEM_BYTES>>>(ctx, Wo, bo, out, kM, kD, kHID);
}

// round 4
// speedup vs baseline: 1.7205x; 1.5029x over previous
#include <cuda_runtime.h>
#include <cuda_bf16.h>
#include <cstdint>
#include <cstddef>

// ===========================================================================
// Problem constants
// ===========================================================================
constexpr int kB   = 2;
constexpr int kS   = 2048;
constexpr int kD   = 1024;
constexpr int kHID = 1024;
constexpr int kH   = 16;
constexpr int kHD  = 64;           // head dim
constexpr int kM   = kB * kS;      // 4096 rows
constexpr float kScale = 0.03125f; // 1/sqrt(1024)

// Scratch buffers (allocation-free rule: __device__ globals)
__device__ float g_q[(size_t)kM * kHID];
__device__ float g_k[(size_t)kM * kHID];
__device__ float g_v[(size_t)kM * kHID];
__device__ float g_ctx[(size_t)kM * kHID];

// ===========================================================================
// mma.sync helpers (sm_80+ baseline features only)
// ===========================================================================
__device__ __forceinline__ uint32_t cvt_tf32(float x) {
    uint32_t r;
    asm("cvt.rna.tf32.f32 %0, %1;" : "=r"(r) : "f"(x));
    return r;
}

__device__ __forceinline__ void split_tf32(float x, uint32_t& h, uint32_t& l) {
    h = cvt_tf32(x);
    l = cvt_tf32(x - __uint_as_float(h));
}

__device__ __forceinline__ void mma_tf32(float* d, const uint32_t* a, const uint32_t* b) {
    asm volatile(
        "mma.sync.aligned.m16n8k8.row.col.f32.tf32.tf32.f32 "
        "{%0,%1,%2,%3}, {%4,%5,%6,%7}, {%8,%9}, {%0,%1,%2,%3};"
        : "+f"(d[0]), "+f"(d[1]), "+f"(d[2]), "+f"(d[3])
        : "r"(a[0]), "r"(a[1]), "r"(a[2]), "r"(a[3]),
          "r"(b[0]), "r"(b[1]));
}

__device__ __forceinline__ void mma_bf16(float* d, const uint32_t* a, const uint32_t* b) {
    asm volatile(
        "mma.sync.aligned.m16n8k16.row.col.f32.bf16.bf16.f32 "
        "{%0,%1,%2,%3}, {%4,%5,%6,%7}, {%8,%9}, {%0,%1,%2,%3};"
        : "+f"(d[0]), "+f"(d[1]), "+f"(d[2]), "+f"(d[3])
        : "r"(a[0]), "r"(a[1]), "r"(a[2]), "r"(a[3]),
          "r"(b[0]), "r"(b[1]));
}

// pack two floats into bf16x2 (x0 -> low, x1 -> high) with hi/lo split
__device__ __forceinline__ void bf16x2_split(float x0, float x1,
                                             uint32_t& hi, uint32_t& lo) {
    __nv_bfloat16 h0 = __float2bfloat16_rn(x0);
    __nv_bfloat16 h1 = __float2bfloat16_rn(x1);
    float r0 = x0 - __bfloat162float(h0);
    float r1 = x1 - __bfloat162float(h1);
    __nv_bfloat16 l0 = __float2bfloat16_rn(r0);
    __nv_bfloat16 l1 = __float2bfloat16_rn(r1);
    hi = ((uint32_t)__bfloat16_as_ushort(h1) << 16) | __bfloat16_as_ushort(h0);
    lo = ((uint32_t)__bfloat16_as_ushort(l1) << 16) | __bfloat16_as_ushort(l0);
}

// ===========================================================================
// 3xTF32 GEMM via mma.sync (unchanged from R3): C = A @ W^T + bias
// ===========================================================================
constexpr int GBK   = 32;
constexpr int KSTR  = 36;
constexpr int TSZ   = 128 * KSTR;
constexpr int BUFSZ = 2 * TSZ;
constexpr int GEMM_SMEM_BYTES = 2 * BUFSZ * 4;

__global__ __launch_bounds__(256, 1)
void gemm_mma_tf32x3(const float* __restrict__ A, const float* __restrict__ W,
                     const float* __restrict__ bias, float* __restrict__ C,
                     int M, int N, int K)
{
    extern __shared__ float smf[];

    const int tid  = threadIdx.x;
    const int wid  = tid >> 5;
    const int lane = tid & 31;
    const int g    = lane >> 2;
    const int t    = lane & 3;

    const int wm = (wid & 3) * 32;
    const int wn = (wid >> 2) * 64;

    const int brow = blockIdx.y * 128;
    const int bcol = blockIdx.x * 128;
    const int nchunks = K / GBK;

    const int lr = tid >> 3;
    const int ls = (tid & 7) * 4;

    const float* Ag = A + (size_t)brow * K + ls;
    const float* Wg = W + (size_t)bcol * K + ls;

    float acc[2][8][4];
    #pragma unroll
    for (int mi = 0; mi < 2; mi++)
        #pragma unroll
        for (int nf = 0; nf < 8; nf++)
            #pragma unroll
            for (int j = 0; j < 4; j++) acc[mi][nf][j] = 0.f;

    float4 pa[4], pb[4];

    #pragma unroll
    for (int i = 0; i < 4; i++) {
        pa[i] = *(const float4*)(Ag + (size_t)(lr + 32 * i) * K);
        pb[i] = *(const float4*)(Wg + (size_t)(lr + 32 * i) * K);
    }
    #pragma unroll
    for (int i = 0; i < 4; i++) {
        *(float4*)(smf + (lr + 32 * i) * KSTR + ls)       = pa[i];
        *(float4*)(smf + TSZ + (lr + 32 * i) * KSTR + ls) = pb[i];
    }
    __syncthreads();

    for (int c = 0; c < nchunks; c++) {
        if (c + 1 < nchunks) {
            const float* Agn = Ag + (size_t)(c + 1) * GBK;
            const float* Wgn = Wg + (size_t)(c + 1) * GBK;
            #pragma unroll
            for (int i = 0; i < 4; i++) {
                pa[i] = *(const float4*)(Agn + (size_t)(lr + 32 * i) * K);
                pb[i] = *(const float4*)(Wgn + (size_t)(lr + 32 * i) * K);
            }
        }

        const float* As = smf + (c & 1) * BUFSZ;
        const float* Bs = As + TSZ;

        #pragma unroll
        for (int kk = 0; kk < 4; kk++) {
            const int k0 = kk * 8;
            uint32_t aH[2][4], aL[2][4];
            #pragma unroll
            for (int mi = 0; mi < 2; mi++) {
                const int m0 = wm + mi * 16;
                float f0 = As[(m0 + g)     * KSTR + k0 + t];
                float f1 = As[(m0 + g + 8) * KSTR + k0 + t];
                float f2 = As[(m0 + g)     * KSTR + k0 + t + 4];
                float f3 = As[(m0 + g + 8) * KSTR + k0 + t + 4];
                split_tf32(f0, aH[mi][0], aL[mi][0]);
                split_tf32(f1, aH[mi][1], aL[mi][1]);
                split_tf32(f2, aH[mi][2], aL[mi][2]);
                split_tf32(f3, aH[mi][3], aL[mi][3]);
            }
            #pragma unroll
            for (int nf = 0; nf < 8; nf++) {
                const int n0 = wn + nf * 8 + g;
                float b0 = Bs[n0 * KSTR + k0 + t];
                float b1 = Bs[n0 * KSTR + k0 + t + 4];
                uint32_t bH[2], bL[2];
                split_tf32(b0, bH[0], bL[0]);
                split_tf32(b1, bH[1], bL[1]);
                #pragma unroll
                for (int mi = 0; mi < 2; mi++) {
                    mma_tf32(acc[mi][nf], aH[mi], bH);
                    mma_tf32(acc[mi][nf], aL[mi], bH);
                    mma_tf32(acc[mi][nf], aH[mi], bL);
                }
            }
        }

        if (c + 1 < nchunks) {
            float* Ad = smf + ((c + 1) & 1) * BUFSZ;
            float* Bd = Ad + TSZ;
            #pragma unroll
            for (int i = 0; i < 4; i++) {
                *(float4*)(Ad + (lr + 32 * i) * KSTR + ls) = pa[i];
                *(float4*)(Bd + (lr + 32 * i) * KSTR + ls) = pb[i];
            }
        }
        __syncthreads();
    }

    #pragma unroll
    for (int mi = 0; mi < 2; mi++) {
        const int r0 = brow + wm + mi * 16 + g;
        #pragma unroll
        for (int nf = 0; nf < 8; nf++) {
            const int c0 = bcol + wn + nf * 8 + 2 * t;
            float2 bi = *(const float2*)(bias + c0);
            float2 v0, v1;
            v0.x = acc[mi][nf][0] + bi.x;
            v0.y = acc[mi][nf][1] + bi.y;
            v1.x = acc[mi][nf][2] + bi.x;
            v1.y = acc[mi][nf][3] + bi.y;
            *(float2*)(C + (size_t)r0 * N + c0)       = v0;
            *(float2*)(C + (size_t)(r0 + 8) * N + c0) = v1;
        }
    }
}

// ===========================================================================
// Tensor-core flash attention (no-max online softmax).
// CTA: 128 queries x one (b,h); 256 threads = 8 warps, warp = 16 q rows.
// KT=64 keys per tile. QK^T in tf32x3, PV in bf16x3 (S-accum packs directly
// into bf16 A-fragments, zero shuffles).
// smem: Qs[128][68] f32 | Khi[64][68] | Klo[64][68] | Vhi,Vlo bf16 [64][72]
// ===========================================================================
constexpr int AKT = 64;
constexpr int QPAD = 68;
constexpr int VPADH = 72;  // halves per hd row (64 keys + 8 pad)
constexpr int ATTN_SMEM_BYTES =
    (128 * QPAD + 2 * 64 * QPAD) * 4 + 2 * 64 * VPADH * 2; // 88,064 B

__global__ __launch_bounds__(256, 1)
void attn_mma(const float* __restrict__ Q, const float* __restrict__ K,
              const float* __restrict__ V, float* __restrict__ O)
{
    extern __shared__ __align__(16) char smem[];
    float*    Qs  = (float*)smem;                      // [128][68]
    float*    Khi = Qs + 128 * QPAD;                   // [64][68]
    float*    Klo = Khi + 64 * QPAD;                   // [64][68]
    uint32_t* VhiW = (uint32_t*)(Klo + 64 * QPAD);     // [64][36] words
    uint32_t* VloW = VhiW + 64 * (VPADH / 2);

    const int tid  = threadIdx.x;
    const int w    = tid >> 5;
    const int lane = tid & 31;
    const int g    = lane >> 2;
    const int t    = lane & 3;

    const int bh = blockIdx.y;
    const int b  = bh >> 4;
    const int h  = bh & 15;
    const int q0 = blockIdx.x * 128;

    // ---- load Q tile (scaled), [q][hd] -> Qs ----
    const float* Qg = Q + (size_t)(b * kS + q0) * kHID + h * kHD;
    #pragma unroll
    for (int i = 0; i < 8; i++) {
        int idx = tid + 256 * i;          // float4 index (2048 total)
        int r = idx >> 4, s4 = (idx & 15) * 4;
        float4 qv = *(const float4*)(Qg + (size_t)r * kHID + s4);
        qv.x *= kScale; qv.y *= kScale; qv.z *= kScale; qv.w *= kScale;
        *(float4*)(Qs + r * QPAD + s4) = qv;
    }
    __syncthreads();

    // ---- resident Q fragments (hi/lo tf32), rows w*16+g, +8 ----
    uint32_t qh[8][4], ql[8][4];
    {
        const float* qr0 = Qs + (w * 16 + g) * QPAD;
        const float* qr1 = qr0 + 8 * QPAD;
        #pragma unroll
        for (int ks = 0; ks < 8; ks++) {
            split_tf32(qr0[ks * 8 + t],     qh[ks][0], ql[ks][0]);
            split_tf32(qr1[ks * 8 + t],     qh[ks][1], ql[ks][1]);
            split_tf32(qr0[ks * 8 + t + 4], qh[ks][2], ql[ks][2]);
            split_tf32(qr1[ks * 8 + t + 4], qh[ks][3], ql[ks][3]);
        }
    }

    float o[8][4];
    #pragma unroll
    for (int nf = 0; nf < 8; nf++)
        #pragma unroll
        for (int e = 0; e < 4; e++) o[nf][e] = 0.f;
    float lsum0 = 0.f, lsum1 = 0.f;

    const float* Kg0 = K + (size_t)(b * kS) * kHID + h * kHD;
    const float* Vg0 = V + (size_t)(b * kS) * kHID + h * kHD;

    for (int kt = 0; kt < kS; kt += AKT) {
        __syncthreads();  // previous tile's smem reads done

        // ---- stage K tile: split hi/lo tf32 into Khi/Klo ----
        const float* Kg = Kg0 + (size_t)kt * kHID;
        #pragma unroll
        for (int i = 0; i < 4; i++) {
            int idx = tid + 256 * i;       // float4 index (1024 total)
            int r = idx >> 4, s4 = (idx & 15) * 4;
            float4 kv = *(const float4*)(Kg + (size_t)r * kHID + s4);
            float4 hi, lo;
            hi.x = __uint_as_float(cvt_tf32(kv.x)); lo.x = __uint_as_float(cvt_tf32(kv.x - hi.x));
            hi.y = __uint_as_float(cvt_tf32(kv.y)); lo.y = __uint_as_float(cvt_tf32(kv.y - hi.y));
            hi.z = __uint_as_float(cvt_tf32(kv.z)); lo.z = __uint_as_float(cvt_tf32(kv.z - hi.z));
            hi.w = __uint_as_float(cvt_tf32(kv.w)); lo.w = __uint_as_float(cvt_tf32(kv.w - hi.w));
            *(float4*)(Khi + r * QPAD + s4) = hi;
            *(float4*)(Klo + r * QPAD + s4) = lo;
        }

        // ---- stage V tile: bf16 hi/lo, transposed [hd][key], packed words ----
        {
            const int kp  = tid & 31;          // key pair -> keys 2kp, 2kp+1
            const int hdb = (tid >> 5) * 8;    // 8 hd values per thread
            const float* v0 = Vg0 + (size_t)(kt + 2 * kp) * kHID + hdb;
            const float* v1 = v0 + kHID;
            float4 a0 = *(const float4*)v0,  a1 = *(const float4*)(v0 + 4);
            float4 b0 = *(const float4*)v1,  b1 = *(const float4*)(v1 + 4);
            float va[8] = {a0.x, a0.y, a0.z, a0.w, a1.x, a1.y, a1.z, a1.w};
            float vb[8] = {b0.x, b0.y, b0.z, b0.w, b1.x, b1.y, b1.z, b1.w};
            #pragma unroll
            for (int j = 0; j < 8; j++) {
                uint32_t hi, lo;
                bf16x2_split(va[j], vb[j], hi, lo);
                VhiW[(hdb + j) * (VPADH / 2) + kp] = hi;
                VloW[(hdb + j) * (VPADH / 2) + kp] = lo;
            }
        }
        __syncthreads();

        // ---- S = Q K^T (tf32x3) ----
        float s[8][4];
        #pragma unroll
        for (int nf = 0; nf < 8; nf++)
            #pragma unroll
            for (int e = 0; e < 4; e++) s[nf][e] = 0.f;

        #pragma unroll
        for (int nf = 0; nf < 8; nf++) {
            const float* kh = Khi + (nf * 8 + g) * QPAD;
            const float* kl = Klo + (nf * 8 + g) * QPAD;
            #pragma unroll
            for (int ks = 0; ks < 8; ks++) {
                uint32_t bH[2], bL[2];
                bH[0] = __float_as_uint(kh[ks * 8 + t]);
                bH[1] = __float_as_uint(kh[ks * 8 + t + 4]);
                bL[0] = __float_as_uint(kl[ks * 8 + t]);
                bL[1] = __float_as_uint(kl[ks * 8 + t + 4]);
                mma_tf32(s[nf], qh[ks], bH);
                mma_tf32(s[nf], ql[ks], bH);
                mma_tf32(s[nf], qh[ks], bL);
            }
        }

        // ---- exp + row-sum + pack P to bf16 hi/lo A-fragments ----
        #pragma unroll
        for (int nf = 0; nf < 8; nf++) {
            float p0 = __expf(s[nf][0]);
            float p1 = __expf(s[nf][1]);
            float p2 = __expf(s[nf][2]);
            float p3 = __expf(s[nf][3]);
            s[nf][0] = p0; s[nf][1] = p1; s[nf][2] = p2; s[nf][3] = p3;
            lsum0 += p0 + p1;
            lsum1 += p2 + p3;
        }
        uint32_t pah[4][4], pal[4][4];
        #pragma unroll
        for (int kc = 0; kc < 4; kc++) {
            bf16x2_split(s[2*kc][0],   s[2*kc][1],   pah[kc][0], pal[kc][0]);
            bf16x2_split(s[2*kc][2],   s[2*kc][3],   pah[kc][1], pal[kc][1]);
            bf16x2_split(s[2*kc+1][0], s[2*kc+1][1], pah[kc][2], pal[kc][2]);
            bf16x2_split(s[2*kc+1][2], s[2*kc+1][3], pah[kc][3], pal[kc][3]);
        }

        // ---- O += P V (bf16x3) ----
        #pragma unroll
        for (int nf = 0; nf < 8; nf++) {
            const uint32_t* vh = VhiW + (nf * 8 + g) * (VPADH / 2);
            const uint32_t* vl = VloW + (nf * 8 + g) * (VPADH / 2);
            #pragma unroll
            for (int kc = 0; kc < 4; kc++) {
                uint32_t bH[2], bL[2];
                bH[0] = vh[kc * 8 + t];
                bH[1] = vh[kc * 8 + t + 4];
                bL[0] = vl[kc * 8 + t];
                bL[1] = vl[kc * 8 + t + 4];
                mma_bf16(o[nf], pah[kc], bH);
                mma_bf16(o[nf], pal[kc], bH);
                mma_bf16(o[nf], pah[kc], bL);
            }
        }
    }

    // ---- final row-sum reduce across quad, normalize, store ----
    lsum0 += __shfl_xor_sync(0xFFFFFFFFu, lsum0, 1);
    lsum0 += __shfl_xor_sync(0xFFFFFFFFu, lsum0, 2);
    lsum1 += __shfl_xor_sync(0xFFFFFFFFu, lsum1, 1);
    lsum1 += __shfl_xor_sync(0xFFFFFFFFu, lsum1, 2);
    const float inv0 = 1.f / lsum0;
    const float inv1 = 1.f / lsum1;

    float* Og = O + (size_t)(b * kS + q0 + w * 16 + g) * kHID + h * kHD;
    #pragma unroll
    for (int nf = 0; nf < 8; nf++) {
        float2 r0, r1;
        r0.x = o[nf][0] * inv0; r0.y = o[nf][1] * inv0;
        r1.x = o[nf][2] * inv1; r1.y = o[nf][3] * inv1;
        *(float2*)(Og + nf * 8 + 2 * t)              = r0;
        *(float2*)(Og + 8 * kHID + nf * 8 + 2 * t)   = r1;
    }
}

// ===========================================================================
// launch
// ===========================================================================
extern "C" void kernel_launch(void* const* d_in, const int* in_sizes, int n_in,
                              void* d_out, int out_size)
{
    const float* x  = (const float*)d_in[0];
    const float* Wq = (const float*)d_in[1];
    const float* bq = (const float*)d_in[2];
    const float* Wk = (const float*)d_in[3];
    const float* bk = (const float*)d_in[4];
    const float* Wv = (const float*)d_in[5];
    const float* bv = (const float*)d_in[6];
    const float* Wo = (const float*)d_in[7];
    const float* bo = (const float*)d_in[8];
    float* out = (float*)d_out;

    float *q, *k, *v, *ctx;
    cudaGetSymbolAddress((void**)&q,   g_q);
    cudaGetSymbolAddress((void**)&k,   g_k);
    cudaGetSymbolAddress((void**)&v,   g_v);
    cudaGetSymbolAddress((void**)&ctx, g_ctx);

    cudaFuncSetAttribute(gemm_mma_tf32x3,
                         cudaFuncAttributeMaxDynamicSharedMemorySize,
                         GEMM_SMEM_BYTES);
    cudaFuncSetAttribute(attn_mma,
                         cudaFuncAttributeMaxDynamicSharedMemorySize,
                         ATTN_SMEM_BYTES);

    dim3 gqkv(kHID / 128, kM / 128); // (8, 32)
    gemm_mma_tf32x3<<<gqkv, 256, GEMM_SMEM_BYTES>>>(x, Wq, bq, q, kM, kHID, kD);
    gemm_mma_tf32x3<<<gqkv, 256, GEMM_SMEM_BYTES>>>(x, Wk, bk, k, kM, kHID, kD);
    gemm_mma_tf32x3<<<gqkv, 256, GEMM_SMEM_BYTES>>>(x, Wv, bv, v, kM, kHID, kD);

    dim3 ga(kS / 128, kB * kH);      // (16, 32)
    attn_mma<<<ga, 256, ATTN_SMEM_BYTES>>>(q, k, v, ctx);

    dim3 go(kD / 128, kM / 128);     // (8, 32)
    gemm_mma_tf32x3<<<go, 256, GEMM_SMEM_BYTES>>>(ctx, Wo, bo, out, kM, kD, kHID);
}

// round 5
// speedup vs baseline: 2.4490x; 1.4234x over previous
#include <cuda_runtime.h>
#include <cuda_bf16.h>
#include <cstdint>
#include <cstddef>

// ===========================================================================
// Problem constants
// ===========================================================================
constexpr int kB   = 2;
constexpr int kS   = 2048;
constexpr int kD   = 1024;
constexpr int kHID = 1024;
constexpr int kH   = 16;
constexpr int kHD  = 64;
constexpr int kM   = kB * kS;      // 4096
constexpr float kScale = 0.03125f; // 1/sqrt(1024), exact power of two

constexpr int kRW   = kD / 2;      // 512 words per row (K=1024 packed)
constexpr int kQKVW = 3 * kRW;     // 1536 words per qkv row

// ===========================================================================
// Scratch (device globals; allocation-free rule)
// ===========================================================================
__device__ uint32_t g_xs_hi [(size_t)kM * kRW];
__device__ uint32_t g_xs_lo [(size_t)kM * kRW];
__device__ uint32_t g_wall_hi[(size_t)3 * kHID * kRW];
__device__ uint32_t g_wall_lo[(size_t)3 * kHID * kRW];
__device__ uint32_t g_wo_hi [(size_t)kD * kRW];
__device__ uint32_t g_wo_lo [(size_t)kD * kRW];
__device__ float    g_bias_all[3 * kHID];
__device__ uint32_t g_qkv_hi[(size_t)kM * kQKVW];
__device__ uint32_t g_qkv_lo[(size_t)kM * kQKVW];
__device__ uint32_t g_ctx_hi[(size_t)kM * kRW];
__device__ uint32_t g_ctx_lo[(size_t)kM * kRW];

// ===========================================================================
// helpers
// ===========================================================================
__device__ __forceinline__ void mma_bf16(float* d, const uint32_t* a, const uint32_t* b) {
    asm volatile(
        "mma.sync.aligned.m16n8k16.row.col.f32.bf16.bf16.f32 "
        "{%0,%1,%2,%3}, {%4,%5,%6,%7}, {%8,%9}, {%0,%1,%2,%3};"
        : "+f"(d[0]), "+f"(d[1]), "+f"(d[2]), "+f"(d[3])
        : "r"(a[0]), "r"(a[1]), "r"(a[2]), "r"(a[3]),
          "r"(b[0]), "r"(b[1]));
}

// pack two floats into bf16x2 word (x0 -> low) + residual word
__device__ __forceinline__ void bf16x2_split(float x0, float x1,
                                             uint32_t& hi, uint32_t& lo) {
    __nv_bfloat16 h0 = __float2bfloat16_rn(x0);
    __nv_bfloat16 h1 = __float2bfloat16_rn(x1);
    float r0 = x0 - __bfloat162float(h0);
    float r1 = x1 - __bfloat162float(h1);
    __nv_bfloat16 l0 = __float2bfloat16_rn(r0);
    __nv_bfloat16 l1 = __float2bfloat16_rn(r1);
    hi = ((uint32_t)__bfloat16_as_ushort(h1) << 16) | __bfloat16_as_ushort(h0);
    lo = ((uint32_t)__bfloat16_as_ushort(l1) << 16) | __bfloat16_as_ushort(l0);
}

__device__ __forceinline__ uint32_t prmt(uint32_t a, uint32_t b, uint32_t sel) {
    uint32_t d;
    asm("prmt.b32 %0, %1, %2, %3;" : "=r"(d) : "r"(a), "r"(b), "r"(sel));
    return d;
}

// ===========================================================================
// split fp32 -> packed bf16 hi/lo words
// ===========================================================================
__global__ void split_kernel(const float* __restrict__ src,
                             uint32_t* __restrict__ hi,
                             uint32_t* __restrict__ lo, int n4)
{
    int i = blockIdx.x * blockDim.x + threadIdx.x;
    if (i >= n4) return;
    float4 v = ((const float4*)src)[i];
    uint32_t h0, l0, h1, l1;
    bf16x2_split(v.x, v.y, h0, l0);
    bf16x2_split(v.z, v.w, h1, l1);
    ((uint2*)hi)[i] = make_uint2(h0, h1);
    ((uint2*)lo)[i] = make_uint2(l0, l1);
}

__global__ void copyf_kernel(const float* __restrict__ src,
                             float* __restrict__ dst, int n)
{
    int i = blockIdx.x * blockDim.x + threadIdx.x;
    if (i < n) dst[i] = src[i];
}

// ===========================================================================
// bf16x3 GEMM: C[M,N] = A[M,K] @ B[N,K]^T + bias
// A,B pre-split packed bf16 pairs (u32 words along K).
// CTA 128x128, BK=32 elems (16 words), 8 warps (4x2), warp 32x64.
// Output: fp32 (Cf) or packed split (Ch/Cl), with optional column scale.
// ===========================================================================
constexpr int GW    = 16;              // words per row per chunk
constexpr int GSTR  = 20;              // padded word stride
constexpr int GT    = 128 * GSTR;      // words per tile array (2560)
constexpr int GSTAGE = 4 * GT;         // AH AL BH BL
constexpr int GEMM_SMEM = 2 * GSTAGE * 4;  // 81920 B

__global__ __launch_bounds__(256, 1)
void gemm_bf16x3(const uint32_t* __restrict__ Ah, const uint32_t* __restrict__ Al,
                 const uint32_t* __restrict__ Bh, const uint32_t* __restrict__ Bl,
                 const float* __restrict__ bias,
                 float* __restrict__ Cf,
                 uint32_t* __restrict__ Ch, uint32_t* __restrict__ Cl,
                 int M, int N, int K, int scaleCols, float scaleVal)
{
    extern __shared__ uint32_t smw[];

    const int tid  = threadIdx.x;
    const int wid  = tid >> 5;
    const int lane = tid & 31;
    const int g    = lane >> 2;
    const int t    = lane & 3;

    const int wm = (wid & 3) * 32;
    const int wn = (wid >> 2) * 64;

    const int brow = blockIdx.y * 128;
    const int bcol = blockIdx.x * 128;
    const int kw   = K >> 1;
    const int nchunks = K / 32;

    // load mapping: 512 uint4 per operand-half; thread does 2 each
    const int lr0 = tid >> 2;            // +64 for second
    const int lw4 = (tid & 3) * 4;

    float acc[2][8][4];
    #pragma unroll
    for (int mi = 0; mi < 2; mi++)
        #pragma unroll
        for (int nf = 0; nf < 8; nf++)
            #pragma unroll
            for (int j = 0; j < 4; j++) acc[mi][nf][j] = 0.f;

    uint4 pAh[2], pAl[2], pBh[2], pBl[2];

    auto ldg_chunk = [&](int c) {
        const uint32_t* a_h = Ah + (size_t)brow * kw + c * GW + lw4;
        const uint32_t* a_l = Al + (size_t)brow * kw + c * GW + lw4;
        const uint32_t* b_h = Bh + (size_t)bcol * kw + c * GW + lw4;
        const uint32_t* b_l = Bl + (size_t)bcol * kw + c * GW + lw4;
        #pragma unroll
        for (int j = 0; j < 2; j++) {
            int r = lr0 + 64 * j;
            pAh[j] = *(const uint4*)(a_h + (size_t)r * kw);
            pAl[j] = *(const uint4*)(a_l + (size_t)r * kw);
            pBh[j] = *(const uint4*)(b_h + (size_t)r * kw);
            pBl[j] = *(const uint4*)(b_l + (size_t)r * kw);
        }
    };
    auto sts_chunk = [&](int buf) {
        uint32_t* s = smw + buf * GSTAGE;
        #pragma unroll
        for (int j = 0; j < 2; j++) {
            int r = lr0 + 64 * j;
            *(uint4*)(s + 0 * GT + r * GSTR + lw4) = pAh[j];
            *(uint4*)(s + 1 * GT + r * GSTR + lw4) = pAl[j];
            *(uint4*)(s + 2 * GT + r * GSTR + lw4) = pBh[j];
            *(uint4*)(s + 3 * GT + r * GSTR + lw4) = pBl[j];
        }
    };

    ldg_chunk(0);
    sts_chunk(0);
    __syncthreads();

    for (int c = 0; c < nchunks; c++) {
        if (c + 1 < nchunks) ldg_chunk(c + 1);

        const uint32_t* AsH = smw + (c & 1) * GSTAGE;
        const uint32_t* AsL = AsH + GT;
        const uint32_t* BsH = AsL + GT;
        const uint32_t* BsL = BsH + GT;

        #pragma unroll
        for (int kk = 0; kk < 2; kk++) {
            const int k0 = kk * 8;
            uint32_t aH[2][4], aL[2][4];
            #pragma unroll
            for (int mi = 0; mi < 2; mi++) {
                const int m0 = wm + mi * 16;
                aH[mi][0] = AsH[(m0 + g)     * GSTR + k0 + t];
                aH[mi][1] = AsH[(m0 + g + 8) * GSTR + k0 + t];
                aH[mi][2] = AsH[(m0 + g)     * GSTR + k0 + t + 4];
                aH[mi][3] = AsH[(m0 + g + 8) * GSTR + k0 + t + 4];
                aL[mi][0] = AsL[(m0 + g)     * GSTR + k0 + t];
                aL[mi][1] = AsL[(m0 + g + 8) * GSTR + k0 + t];
                aL[mi][2] = AsL[(m0 + g)     * GSTR + k0 + t + 4];
                aL[mi][3] = AsL[(m0 + g + 8) * GSTR + k0 + t + 4];
            }
            #pragma unroll
            for (int nf = 0; nf < 8; nf++) {
                const int n0 = wn + nf * 8 + g;
                uint32_t bH[2], bL[2];
                bH[0] = BsH[n0 * GSTR + k0 + t];
                bH[1] = BsH[n0 * GSTR + k0 + t + 4];
                bL[0] = BsL[n0 * GSTR + k0 + t];
                bL[1] = BsL[n0 * GSTR + k0 + t + 4];
                #pragma unroll
                for (int mi = 0; mi < 2; mi++) {
                    mma_bf16(acc[mi][nf], aH[mi], bH);
                    mma_bf16(acc[mi][nf], aL[mi], bH);
                    mma_bf16(acc[mi][nf], aH[mi], bL);
                }
            }
        }

        if (c + 1 < nchunks) sts_chunk((c + 1) & 1);
        __syncthreads();
    }

    // epilogue
    const int nw = N >> 1;
    #pragma unroll
    for (int mi = 0; mi < 2; mi++) {
        const int r0 = brow + wm + mi * 16 + g;
        #pragma unroll
        for (int nf = 0; nf < 8; nf++) {
            const int c0 = bcol + wn + nf * 8 + 2 * t;
            float bx = bias[c0], by = bias[c0 + 1];
            float v0 = acc[mi][nf][0] + bx, v1 = acc[mi][nf][1] + by;
            float v2 = acc[mi][nf][2] + bx, v3 = acc[mi][nf][3] + by;
            if (Cf) {
                *(float2*)(Cf + (size_t)r0 * N + c0)       = make_float2(v0, v1);
                *(float2*)(Cf + (size_t)(r0 + 8) * N + c0) = make_float2(v2, v3);
            } else {
                float sc = (c0 < scaleCols) ? scaleVal : 1.0f;
                v0 *= sc; v1 *= sc; v2 *= sc; v3 *= sc;
                uint32_t h, l;
                bf16x2_split(v0, v1, h, l);
                Ch[(size_t)r0 * nw + (c0 >> 1)] = h;
                Cl[(size_t)r0 * nw + (c0 >> 1)] = l;
                bf16x2_split(v2, v3, h, l);
                Ch[(size_t)(r0 + 8) * nw + (c0 >> 1)] = h;
                Cl[(size_t)(r0 + 8) * nw + (c0 >> 1)] = l;
            }
        }
    }
}

// ===========================================================================
// bf16x3 flash attention (no-max softmax; Q pre-scaled by 1/32 at projection).
// CTA = 128 queries x (b,h); 256 thr / 8 warps; KT=64; double-buffered K/V.
// Input qkv packed hi/lo words: row = token [1536 words]: Q | K | V per head.
// Output ctx packed hi/lo [token][512 words].
// ===========================================================================
constexpr int QSTR = 36;       // padded word stride (32 + 4)
constexpr int AT_Q  = 128 * QSTR;            // per half
constexpr int AT_KV = 64 * QSTR;             // per array
// layout words: QH, QL, stage0{KH,KL,VH,VL}, stage1{...}
constexpr int AT_STAGE = 4 * AT_KV;
constexpr int ATTN_SMEM = (2 * AT_Q + 2 * AT_STAGE) * 4;  // 110,592 B

__global__ __launch_bounds__(256, 1)
void attn_bf16(const uint32_t* __restrict__ Qh, const uint32_t* __restrict__ Ql,
               uint32_t* __restrict__ Oh, uint32_t* __restrict__ Ol)
{
    extern __shared__ uint32_t smw[];
    uint32_t* QH = smw;
    uint32_t* QL = QH + AT_Q;
    uint32_t* ST = QL + AT_Q;   // 2 stages

    const int tid  = threadIdx.x;
    const int w    = tid >> 5;
    const int lane = tid & 31;
    const int g    = lane >> 2;
    const int t    = lane & 3;

    const int bh = blockIdx.y;
    const int b  = bh >> 4;
    const int h  = bh & 15;
    const int q0 = blockIdx.x * 128;

    const size_t rowbase = (size_t)(b * kS) * kQKVW;
    const int qoff = h * 32;
    const int koff = 512 + h * 32;
    const int voff = 1024 + h * 32;

    // ---- stage Q (hi/lo packed words) ----
    {
        const uint32_t* qh = Qh + rowbase + (size_t)q0 * kQKVW + qoff;
        const uint32_t* ql = Ql + rowbase + (size_t)q0 * kQKVW + qoff;
        #pragma unroll
        for (int i = 0; i < 4; i++) {
            int idx = tid + 256 * i;
            int r = idx >> 3, w4 = (idx & 7) * 4;
            *(uint4*)(QH + r * QSTR + w4) = *(const uint4*)(qh + (size_t)r * kQKVW + w4);
            *(uint4*)(QL + r * QSTR + w4) = *(const uint4*)(ql + (size_t)r * kQKVW + w4);
        }
    }
    __syncthreads();

    // ---- resident Q fragments ----
    uint32_t qHf[4][4], qLf[4][4];
    {
        const int r0 = (w * 16 + g) * QSTR;
        const int r1 = r0 + 8 * QSTR;
        #pragma unroll
        for (int ks = 0; ks < 4; ks++) {
            const int k0 = ks * 8;
            qHf[ks][0] = QH[r0 + k0 + t];
            qHf[ks][1] = QH[r1 + k0 + t];
            qHf[ks][2] = QH[r0 + k0 + t + 4];
            qHf[ks][3] = QH[r1 + k0 + t + 4];
            qLf[ks][0] = QL[r0 + k0 + t];
            qLf[ks][1] = QL[r1 + k0 + t];
            qLf[ks][2] = QL[r0 + k0 + t + 4];
            qLf[ks][3] = QL[r1 + k0 + t + 4];
        }
    }

    float o[8][4];
    #pragma unroll
    for (int nf = 0; nf < 8; nf++)
        #pragma unroll
        for (int e = 0; e < 4; e++) o[nf][e] = 0.f;
    float lsum0 = 0.f, lsum1 = 0.f;

    // K/V prefetch registers
    uint4 pKh[2], pKl[2], pV[4];
    const int kr  = tid >> 3;           // +0: rows 0..31 pattern (idx>>3)
    const int kw4 = (tid & 7) * 4;
    const int kp  = lane;               // V: key pair id (0..31)
    const int wb  = w * 4;              // V: word block (hd words wb..wb+3)

    auto ldg_tile = [&](int kt) {
        const uint32_t* khp = Qh + rowbase + (size_t)kt * kQKVW + koff;
        const uint32_t* klp = Ql + rowbase + (size_t)kt * kQKVW + koff;
        #pragma unroll
        for (int i = 0; i < 2; i++) {
            int r = kr + 32 * i;
            pKh[i] = *(const uint4*)(khp + (size_t)r * kQKVW + kw4);
            pKl[i] = *(const uint4*)(klp + (size_t)r * kQKVW + kw4);
        }
        const uint32_t* v0h = Qh + rowbase + (size_t)(kt + 2 * kp) * kQKVW + voff + wb;
        const uint32_t* v0l = Ql + rowbase + (size_t)(kt + 2 * kp) * kQKVW + voff + wb;
        pV[0] = *(const uint4*)v0h;
        pV[1] = *(const uint4*)(v0h + kQKVW);
        pV[2] = *(const uint4*)v0l;
        pV[3] = *(const uint4*)(v0l + kQKVW);
    };
    auto sts_tile = [&](int buf) {
        uint32_t* KHs = ST + buf * AT_STAGE;
        uint32_t* KLs = KHs + AT_KV;
        uint32_t* VHs = KLs + AT_KV;
        uint32_t* VLs = VHs + AT_KV;
        #pragma unroll
        for (int i = 0; i < 2; i++) {
            int r = kr + 32 * i;
            *(uint4*)(KHs + r * QSTR + kw4) = pKh[i];
            *(uint4*)(KLs + r * QSTR + kw4) = pKl[i];
        }
        // V transpose repack: words [key][hd-pair] -> [hd][key-pair]
        const uint32_t vh0[4] = {pV[0].x, pV[0].y, pV[0].z, pV[0].w};
        const uint32_t vh1[4] = {pV[1].x, pV[1].y, pV[1].z, pV[1].w};
        const uint32_t vl0[4] = {pV[2].x, pV[2].y, pV[2].z, pV[2].w};
        const uint32_t vl1[4] = {pV[3].x, pV[3].y, pV[3].z, pV[3].w};
        #pragma unroll
        for (int j = 0; j < 4; j++) {
            int hd = 2 * (wb + j);
            VHs[hd * QSTR + kp]       = prmt(vh0[j], vh1[j], 0x5410);
            VHs[(hd + 1) * QSTR + kp] = prmt(vh0[j], vh1[j], 0x7632);
            VLs[hd * QSTR + kp]       = prmt(vl0[j], vl1[j], 0x5410);
            VLs[(hd + 1) * QSTR + kp] = prmt(vl0[j], vl1[j], 0x7632);
        }
    };

    ldg_tile(0);
    sts_tile(0);
    __syncthreads();

    for (int tI = 0; tI < kS / 64; tI++) {
        if (tI + 1 < kS / 64) ldg_tile((tI + 1) * 64);

        const uint32_t* KHs = ST + (tI & 1) * AT_STAGE;
        const uint32_t* KLs = KHs + AT_KV;
        const uint32_t* VHs = KLs + AT_KV;
        const uint32_t* VLs = VHs + AT_KV;

        // ---- S = Q K^T (bf16x3) ----
        float s[8][4];
        #pragma unroll
        for (int nf = 0; nf < 8; nf++) {
            s[nf][0] = s[nf][1] = s[nf][2] = s[nf][3] = 0.f;
            const int n0 = (nf * 8 + g) * QSTR;
            #pragma unroll
            for (int ks = 0; ks < 4; ks++) {
                const int k0 = ks * 8;
                uint32_t bH[2], bL[2];
                bH[0] = KHs[n0 + k0 + t];
                bH[1] = KHs[n0 + k0 + t + 4];
                bL[0] = KLs[n0 + k0 + t];
                bL[1] = KLs[n0 + k0 + t + 4];
                mma_bf16(s[nf], qHf[ks], bH);
                mma_bf16(s[nf], qLf[ks], bH);
                mma_bf16(s[nf], qHf[ks], bL);
            }
        }

        // ---- exp + row-sum + pack P ----
        uint32_t pah[4][4], pal[4][4];
        #pragma unroll
        for (int nf = 0; nf < 8; nf++) {
            float p0 = __expf(s[nf][0]);
            float p1 = __expf(s[nf][1]);
            float p2 = __expf(s[nf][2]);
            float p3 = __expf(s[nf][3]);
            s[nf][0] = p0; s[nf][1] = p1; s[nf][2] = p2; s[nf][3] = p3;
            lsum0 += p0 + p1;
            lsum1 += p2 + p3;
        }
        #pragma unroll
        for (int kc = 0; kc < 4; kc++) {
            bf16x2_split(s[2*kc][0],   s[2*kc][1],   pah[kc][0], pal[kc][0]);
            bf16x2_split(s[2*kc][2],   s[2*kc][3],   pah[kc][1], pal[kc][1]);
            bf16x2_split(s[2*kc+1][0], s[2*kc+1][1], pah[kc][2], pal[kc][2]);
            bf16x2_split(s[2*kc+1][2], s[2*kc+1][3], pah[kc][3], pal[kc][3]);
        }

        // ---- O += P V (bf16x3) ----
        #pragma unroll
        for (int nf = 0; nf < 8; nf++) {
            const int n0 = (nf * 8 + g) * QSTR;
            #pragma unroll
            for (int kc = 0; kc < 4; kc++) {
                const int k0 = kc * 8;
                uint32_t bH[2], bL[2];
                bH[0] = VHs[n0 + k0 + t];
                bH[1] = VHs[n0 + k0 + t + 4];
                bL[0] = VLs[n0 + k0 + t];
                bL[1] = VLs[n0 + k0 + t + 4];
                mma_bf16(o[nf], pah[kc], bH);
                mma_bf16(o[nf], pal[kc], bH);
                mma_bf16(o[nf], pah[kc], bL);
            }
        }

        if (tI + 1 < kS / 64) sts_tile((tI + 1) & 1);
        __syncthreads();
    }

    // ---- reduce, normalize, split-pack, store ctx ----
    lsum0 += __shfl_xor_sync(0xFFFFFFFFu, lsum0, 1);
    lsum0 += __shfl_xor_sync(0xFFFFFFFFu, lsum0, 2);
    lsum1 += __shfl_xor_sync(0xFFFFFFFFu, lsum1, 1);
    lsum1 += __shfl_xor_sync(0xFFFFFFFFu, lsum1, 2);
    const float inv0 = 1.f / lsum0;
    const float inv1 = 1.f / lsum1;

    const size_t row0 = (size_t)(b * kS + q0 + w * 16 + g);
    #pragma unroll
    for (int nf = 0; nf < 8; nf++) {
        const int cw = h * 32 + nf * 4 + t;
        uint32_t hw, lw;
        bf16x2_split(o[nf][0] * inv0, o[nf][1] * inv0, hw, lw);
        Oh[row0 * kRW + cw] = hw;
        Ol[row0 * kRW + cw] = lw;
        bf16x2_split(o[nf][2] * inv1, o[nf][3] * inv1, hw, lw);
        Oh[(row0 + 8) * kRW + cw] = hw;
        Ol[(row0 + 8) * kRW + cw] = lw;
    }
}

// ===========================================================================
// launch
// ===========================================================================
extern "C" void kernel_launch(void* const* d_in, const int* in_sizes, int n_in,
                              void* d_out, int out_size)
{
    const float* x  = (const float*)d_in[0];
    const float* Wq = (const float*)d_in[1];
    const float* bq = (const float*)d_in[2];
    const float* Wk = (const float*)d_in[3];
    const float* bk = (const float*)d_in[4];
    const float* Wv = (const float*)d_in[5];
    const float* bv = (const float*)d_in[6];
    const float* Wo = (const float*)d_in[7];
    const float* bo = (const float*)d_in[8];
    float* out = (float*)d_out;

    uint32_t *xs_hi, *xs_lo, *wall_hi, *wall_lo, *wo_hi, *wo_lo;
    uint32_t *qkv_hi, *qkv_lo, *ctx_hi, *ctx_lo;
    float* bias_all;
    cudaGetSymbolAddress((void**)&xs_hi,   g_xs_hi);
    cudaGetSymbolAddress((void**)&xs_lo,   g_xs_lo);
    cudaGetSymbolAddress((void**)&wall_hi, g_wall_hi);
    cudaGetSymbolAddress((void**)&wall_lo, g_wall_lo);
    cudaGetSymbolAddress((void**)&wo_hi,   g_wo_hi);
    cudaGetSymbolAddress((void**)&wo_lo,   g_wo_lo);
    cudaGetSymbolAddress((void**)&bias_all,g_bias_all);
    cudaGetSymbolAddress((void**)&qkv_hi,  g_qkv_hi);
    cudaGetSymbolAddress((void**)&qkv_lo,  g_qkv_lo);
    cudaGetSymbolAddress((void**)&ctx_hi,  g_ctx_hi);
    cudaGetSymbolAddress((void**)&ctx_lo,  g_ctx_lo);

    cudaFuncSetAttribute(gemm_bf16x3,
                         cudaFuncAttributeMaxDynamicSharedMemorySize, GEMM_SMEM);
    cudaFuncSetAttribute(attn_bf16,
                         cudaFuncAttributeMaxDynamicSharedMemorySize, ATTN_SMEM);

    const int wq4 = kHID * kD / 4;   // 262144
    split_kernel<<<kM * kD / 4 / 256, 256>>>(x, xs_hi, xs_lo, kM * kD / 4);
    split_kernel<<<wq4 / 256, 256>>>(Wq, wall_hi,                 wall_lo,                 wq4);
    split_kernel<<<wq4 / 256, 256>>>(Wk, wall_hi + (size_t)kHID * kRW, wall_lo + (size_t)kHID * kRW, wq4);
    split_kernel<<<wq4 / 256, 256>>>(Wv, wall_hi + (size_t)2 * kHID * kRW, wall_lo + (size_t)2 * kHID * kRW, wq4);
    split_kernel<<<wq4 / 256, 256>>>(Wo, wo_hi, wo_lo, wq4);
    copyf_kernel<<<4, 256>>>(bq, bias_all,            kHID);
    copyf_kernel<<<4, 256>>>(bk, bias_all + kHID,     kHID);
    copyf_kernel<<<4, 256>>>(bv, bias_all + 2 * kHID, kHID);

    // fused QKV projection: M=4096, N=3072 (Q scaled by 1/32 in epilogue)
    dim3 gqkv(3 * kHID / 128, kM / 128);   // (24, 32)
    gemm_bf16x3<<<gqkv, 256, GEMM_SMEM>>>(
        xs_hi, xs_lo, wall_hi, wall_lo, bias_all,
        nullptr, qkv_hi, qkv_lo, kM, 3 * kHID, kD, kHID, kScale);

    dim3 ga(kS / 128, kB * kH);            // (16, 32)
    attn_bf16<<<ga, 256, ATTN_SMEM>>>(qkv_hi, qkv_lo, ctx_hi, ctx_lo);

    dim3 go(kD / 128, kM / 128);           // (8, 32)
    gemm_bf16x3<<<go, 256, GEMM_SMEM>>>(
        ctx_hi, ctx_lo, wo_hi, wo_lo, bo,
        out, nullptr, nullptr, kM, kD, kHID, 0, 1.0f);
}

// round 8
// speedup vs baseline: 2.9805x; 1.2170x over previous
#include <cuda_runtime.h>
#include <cuda_bf16.h>
#include <cstdint>
#include <cstddef>

// ===========================================================================
// Problem constants
// ===========================================================================
constexpr int kB   = 2;
constexpr int kS   = 2048;
constexpr int kD   = 1024;
constexpr int kHID = 1024;
constexpr int kH   = 16;
constexpr int kHD  = 64;
constexpr int kM   = kB * kS;      // 4096
constexpr float kScale = 0.03125f; // 1/sqrt(1024), exact power of two

constexpr int kRW   = kD / 2;      // 512 words per row (K=1024 packed)
constexpr int kQKVW = 3 * kRW;     // 1536 words per qkv row

// ===========================================================================
// Scratch (device globals; allocation-free rule)
// ===========================================================================
__device__ uint32_t g_xs_hi [(size_t)kM * kRW];
__device__ uint32_t g_xs_lo [(size_t)kM * kRW];
__device__ uint32_t g_wall_hi[(size_t)3 * kHID * kRW];
__device__ uint32_t g_wall_lo[(size_t)3 * kHID * kRW];
__device__ uint32_t g_wo_hi [(size_t)kD * kRW];
__device__ uint32_t g_wo_lo [(size_t)kD * kRW];
__device__ float    g_bias_all[3 * kHID];
__device__ uint32_t g_qkv_hi[(size_t)kM * kQKVW];
__device__ uint32_t g_qkv_lo[(size_t)kM * kQKVW];
__device__ uint32_t g_ctx_hi[(size_t)kM * kRW];
__device__ uint32_t g_ctx_lo[(size_t)kM * kRW];

// ===========================================================================
// helpers
// ===========================================================================
__device__ __forceinline__ void mma_bf16(float* d, const uint32_t* a, const uint32_t* b) {
    asm volatile(
        "mma.sync.aligned.m16n8k16.row.col.f32.bf16.bf16.f32 "
        "{%0,%1,%2,%3}, {%4,%5,%6,%7}, {%8,%9}, {%0,%1,%2,%3};"
        : "+f"(d[0]), "+f"(d[1]), "+f"(d[2]), "+f"(d[3])
        : "r"(a[0]), "r"(a[1]), "r"(a[2]), "r"(a[3]),
          "r"(b[0]), "r"(b[1]));
}

__device__ __forceinline__ void ldsm_x4(uint32_t& r0, uint32_t& r1,
                                        uint32_t& r2, uint32_t& r3, uint32_t addr) {
    asm volatile(
        "ldmatrix.sync.aligned.m8n8.x4.shared.b16 {%0,%1,%2,%3}, [%4];"
        : "=r"(r0), "=r"(r1), "=r"(r2), "=r"(r3) : "r"(addr));
}

__device__ __forceinline__ uint32_t smem_u32(const void* p) {
    uint32_t a;
    asm("{ .reg .u64 t; cvta.to.shared.u64 t, %1; cvt.u32.u64 %0, t; }"
        : "=r"(a) : "l"(p));
    return a;
}

// pack two floats into bf16x2 word (x0 -> low) + residual word
__device__ __forceinline__ void bf16x2_split(float x0, float x1,
                                             uint32_t& hi, uint32_t& lo) {
    __nv_bfloat16 h0 = __float2bfloat16_rn(x0);
    __nv_bfloat16 h1 = __float2bfloat16_rn(x1);
    float r0 = x0 - __bfloat162float(h0);
    float r1 = x1 - __bfloat162float(h1);
    __nv_bfloat16 l0 = __float2bfloat16_rn(r0);
    __nv_bfloat16 l1 = __float2bfloat16_rn(r1);
    hi = ((uint32_t)__bfloat16_as_ushort(h1) << 16) | __bfloat16_as_ushort(h0);
    lo = ((uint32_t)__bfloat16_as_ushort(l1) << 16) | __bfloat16_as_ushort(l0);
}

__device__ __forceinline__ uint32_t prmt(uint32_t a, uint32_t b, uint32_t sel) {
    uint32_t d;
    asm("prmt.b32 %0, %1, %2, %3;" : "=r"(d) : "r"(a), "r"(b), "r"(sel));
    return d;
}

// ===========================================================================
// split fp32 -> packed bf16 hi/lo words
// ===========================================================================
__global__ void split_kernel(const float* __restrict__ src,
                             uint32_t* __restrict__ hi,
                             uint32_t* __restrict__ lo, int n4)
{
    int i = blockIdx.x * blockDim.x + threadIdx.x;
    if (i >= n4) return;
    float4 v = ((const float4*)src)[i];
    uint32_t h0, l0, h1, l1;
    bf16x2_split(v.x, v.y, h0, l0);
    bf16x2_split(v.z, v.w, h1, l1);
    ((uint2*)hi)[i] = make_uint2(h0, h1);
    ((uint2*)lo)[i] = make_uint2(l0, l1);
}

__global__ void copyf_kernel(const float* __restrict__ src,
                             float* __restrict__ dst, int n)
{
    int i = blockIdx.x * blockDim.x + threadIdx.x;
    if (i < n) dst[i] = src[i];
}

// ===========================================================================
// bf16x3 GEMM: C[M,N] = A[M,K] @ B[N,K]^T + bias
// aH bH + aL bH + aH bL; A,B pre-split packed bf16 pairs.
// CTA 128x128, BK=32 elems (16 words), 8 warps (4x2), warp 32x64.
// Fragment loads via ldmatrix.x4.
// ===========================================================================
constexpr int GW    = 16;              // words per row per chunk
constexpr int GSTR  = 20;              // padded word stride
constexpr int GT    = 128 * GSTR;      // words per tile array (2560)
constexpr int GSTAGE = 4 * GT;
constexpr int GEMM_SMEM = 2 * GSTAGE * 4;   // 81920 B

__global__ __launch_bounds__(256, 1)
void gemm_bf16x3(const uint32_t* __restrict__ Ah, const uint32_t* __restrict__ Al,
                 const uint32_t* __restrict__ Bh, const uint32_t* __restrict__ Bl,
                 const float* __restrict__ bias,
                 float* __restrict__ Cf,
                 uint32_t* __restrict__ Ch, uint32_t* __restrict__ Cl,
                 int M, int N, int K, int scaleCols, float scaleVal)
{
    extern __shared__ uint32_t smw[];
    const uint32_t sb = smem_u32(smw);

    const int tid  = threadIdx.x;
    const int wid  = tid >> 5;
    const int lane = tid & 31;
    const int g    = lane >> 2;
    const int t    = lane & 3;

    const int wm = (wid & 3) * 32;
    const int wn = (wid >> 2) * 64;

    // ldmatrix lane constants
    const int lm8 = lane & 7;
    const int lq  = lane >> 3;
    const int a_row = lm8 + (lq & 1) * 8;   // A: matrices (r0,k0),(r8,k0),(r0,k4),(r8,k4)
    const int a_wof = (lq >> 1) * 4;
    const int b_row = lm8 + (lq >> 1) * 8;  // B: matrices (n0,k0),(n0,k4),(n8,k0),(n8,k4)
    const int b_wof = (lq & 1) * 4;

    const int brow = blockIdx.y * 128;
    const int bcol = blockIdx.x * 128;
    const int kw   = K >> 1;
    const int nchunks = K / 32;

    const int lr0 = tid >> 2;            // +64 for second
    const int lw4 = (tid & 3) * 4;

    float acc[2][8][4];
    #pragma unroll
    for (int mi = 0; mi < 2; mi++)
        #pragma unroll
        for (int nf = 0; nf < 8; nf++)
            #pragma unroll
            for (int j = 0; j < 4; j++) acc[mi][nf][j] = 0.f;

    uint4 pAh[2], pAl[2], pBh[2], pBl[2];

    auto ldg_chunk = [&](int c) {
        const uint32_t* a_h = Ah + (size_t)brow * kw + c * GW + lw4;
        const uint32_t* a_l = Al + (size_t)brow * kw + c * GW + lw4;
        const uint32_t* b_h = Bh + (size_t)bcol * kw + c * GW + lw4;
        const uint32_t* b_l = Bl + (size_t)bcol * kw + c * GW + lw4;
        #pragma unroll
        for (int j = 0; j < 2; j++) {
            int r = lr0 + 64 * j;
            pAh[j] = *(const uint4*)(a_h + (size_t)r * kw);
            pAl[j] = *(const uint4*)(a_l + (size_t)r * kw);
            pBh[j] = *(const uint4*)(b_h + (size_t)r * kw);
            pBl[j] = *(const uint4*)(b_l + (size_t)r * kw);
        }
    };
    auto sts_chunk = [&](int buf) {
        uint32_t* s = smw + buf * GSTAGE;
        #pragma unroll
        for (int j = 0; j < 2; j++) {
            int r = lr0 + 64 * j;
            *(uint4*)(s + 0 * GT + r * GSTR + lw4) = pAh[j];
            *(uint4*)(s + 1 * GT + r * GSTR + lw4) = pAl[j];
            *(uint4*)(s + 2 * GT + r * GSTR + lw4) = pBh[j];
            *(uint4*)(s + 3 * GT + r * GSTR + lw4) = pBl[j];
        }
    };

    ldg_chunk(0);
    sts_chunk(0);
    __syncthreads();

    for (int c = 0; c < nchunks; c++) {
        if (c + 1 < nchunks) ldg_chunk(c + 1);

        const uint32_t base = sb + (uint32_t)(((c & 1) * GSTAGE) << 2);

        #pragma unroll
        for (int kk = 0; kk < 2; kk++) {
            const int k0 = kk * 8;
            uint32_t aH[2][4], aL[2][4];
            #pragma unroll
            for (int mi = 0; mi < 2; mi++) {
                uint32_t arow = (uint32_t)((wm + mi * 16 + a_row) * GSTR + k0 + a_wof);
                ldsm_x4(aH[mi][0], aH[mi][1], aH[mi][2], aH[mi][3],
                        base + ((0 * GT + arow) << 2));
                ldsm_x4(aL[mi][0], aL[mi][1], aL[mi][2], aL[mi][3],
                        base + ((1 * GT + arow) << 2));
            }
            #pragma unroll
            for (int np = 0; np < 4; np++) {
                uint32_t nrow = (uint32_t)((wn + np * 16 + b_row) * GSTR + k0 + b_wof);
                uint32_t bh[4], bl[4];
                ldsm_x4(bh[0], bh[1], bh[2], bh[3], base + ((2 * GT + nrow) << 2));
                ldsm_x4(bl[0], bl[1], bl[2], bl[3], base + ((3 * GT + nrow) << 2));
                #pragma unroll
                for (int half = 0; half < 2; half++) {
                    const int nf = np * 2 + half;
                    #pragma unroll
                    for (int mi = 0; mi < 2; mi++) {
                        mma_bf16(acc[mi][nf], aH[mi], bh + 2 * half);
                        mma_bf16(acc[mi][nf], aH[mi], bl + 2 * half);
                        mma_bf16(acc[mi][nf], aL[mi], bh + 2 * half);
                    }
                }
            }
        }

        if (c + 1 < nchunks) sts_chunk((c + 1) & 1);
        __syncthreads();
    }

    // epilogue
    const int nw = N >> 1;
    #pragma unroll
    for (int mi = 0; mi < 2; mi++) {
        const int r0 = brow + wm + mi * 16 + g;
        #pragma unroll
        for (int nf = 0; nf < 8; nf++) {
            const int c0 = bcol + wn + nf * 8 + 2 * t;
            float bx = bias[c0], by = bias[c0 + 1];
            float v0 = acc[mi][nf][0] + bx, v1 = acc[mi][nf][1] + by;
            float v2 = acc[mi][nf][2] + bx, v3 = acc[mi][nf][3] + by;
            if (Cf) {
                *(float2*)(Cf + (size_t)r0 * N + c0)       = make_float2(v0, v1);
                *(float2*)(Cf + (size_t)(r0 + 8) * N + c0) = make_float2(v2, v3);
            } else {
                float sc = (c0 < scaleCols) ? scaleVal : 1.0f;
                v0 *= sc; v1 *= sc; v2 *= sc; v3 *= sc;
                uint32_t h, l;
                bf16x2_split(v0, v1, h, l);
                Ch[(size_t)r0 * nw + (c0 >> 1)] = h;
                Cl[(size_t)r0 * nw + (c0 >> 1)] = l;
                bf16x2_split(v2, v3, h, l);
                Ch[(size_t)(r0 + 8) * nw + (c0 >> 1)] = h;
                Cl[(size_t)(r0 + 8) * nw + (c0 >> 1)] = l;
            }
        }
    }
}

// ===========================================================================
// bf16x3 flash attention (no-max softmax; Q pre-scaled by 1/32 at projection).
// QK^T: qH kH + qL kH + qH kL (3 mma). PV: pH vH + pL vH + pH vL (3 mma).
// Fragment loads via ldmatrix.x4. CTA = 128 q x (b,h); 256 thr; KT=64; 2-stage.
// ===========================================================================
constexpr int QSTR = 36;                     // padded word stride
constexpr int AT_Q  = 128 * QSTR;            // per half (hi or lo)
constexpr int AT_KV = 64 * QSTR;
constexpr int AT_STAGE = 4 * AT_KV;          // KH KL VH VL
constexpr int ATTN_SMEM = (2 * AT_Q + 2 * AT_STAGE) * 4;  // 110,592 B

__global__ __launch_bounds__(256, 1)
void attn_bf16(const uint32_t* __restrict__ Qh, const uint32_t* __restrict__ Ql,
               uint32_t* __restrict__ Oh, uint32_t* __restrict__ Ol)
{
    extern __shared__ uint32_t smw[];
    uint32_t* QH = smw;
    uint32_t* QL = QH + AT_Q;
    uint32_t* ST = QL + AT_Q;   // 2 stages
    const uint32_t sb = smem_u32(smw);

    const int tid  = threadIdx.x;
    const int w    = tid >> 5;
    const int lane = tid & 31;
    const int g    = lane >> 2;
    const int t    = lane & 3;

    const int lm8 = lane & 7;
    const int lq  = lane >> 3;
    const int b_row = lm8 + (lq >> 1) * 8;
    const int b_wof = (lq & 1) * 4;

    const int bh = blockIdx.y;
    const int b  = bh >> 4;
    const int h  = bh & 15;
    const int q0 = blockIdx.x * 128;

    const size_t rowbase = (size_t)(b * kS) * kQKVW;
    const int qoff = h * 32;
    const int koff = 512 + h * 32;
    const int voff = 1024 + h * 32;

    // ---- stage Q (hi + lo words) ----
    {
        const uint32_t* qh = Qh + rowbase + (size_t)q0 * kQKVW + qoff;
        const uint32_t* ql = Ql + rowbase + (size_t)q0 * kQKVW + qoff;
        #pragma unroll
        for (int i = 0; i < 4; i++) {
            int idx = tid + 256 * i;
            int r = idx >> 3, w4 = (idx & 7) * 4;
            *(uint4*)(QH + r * QSTR + w4) = *(const uint4*)(qh + (size_t)r * kQKVW + w4);
            *(uint4*)(QL + r * QSTR + w4) = *(const uint4*)(ql + (size_t)r * kQKVW + w4);
        }
    }
    __syncthreads();

    // ---- resident Q fragments (hi + lo) ----
    uint32_t qHf[4][4], qLf[4][4];
    {
        const int r0 = (w * 16 + g) * QSTR;
        const int r1 = r0 + 8 * QSTR;
        #pragma unroll
        for (int ks = 0; ks < 4; ks++) {
            const int k0 = ks * 8;
            qHf[ks][0] = QH[r0 + k0 + t];
            qHf[ks][1] = QH[r1 + k0 + t];
            qHf[ks][2] = QH[r0 + k0 + t + 4];
            qHf[ks][3] = QH[r1 + k0 + t + 4];
            qLf[ks][0] = QL[r0 + k0 + t];
            qLf[ks][1] = QL[r1 + k0 + t];
            qLf[ks][2] = QL[r0 + k0 + t + 4];
            qLf[ks][3] = QL[r1 + k0 + t + 4];
        }
    }

    float o[8][4];
    #pragma unroll
    for (int nf = 0; nf < 8; nf++)
        #pragma unroll
        for (int e = 0; e < 4; e++) o[nf][e] = 0.f;
    float lsum0 = 0.f, lsum1 = 0.f;

    // K/V prefetch registers
    uint4 pKh[2], pKl[2], pV[4];
    const int kr  = tid >> 3;
    const int kw4 = (tid & 7) * 4;
    const int kp  = lane;               // V: key pair id
    const int wb  = w * 4;              // V: word block

    auto ldg_tile = [&](int kt) {
        const uint32_t* khp = Qh + rowbase + (size_t)kt * kQKVW + koff;
        const uint32_t* klp = Ql + rowbase + (size_t)kt * kQKVW + koff;
        #pragma unroll
        for (int i = 0; i < 2; i++) {
            int r = kr + 32 * i;
            pKh[i] = *(const uint4*)(khp + (size_t)r * kQKVW + kw4);
            pKl[i] = *(const uint4*)(klp + (size_t)r * kQKVW + kw4);
        }
        const uint32_t* v0h = Qh + rowbase + (size_t)(kt + 2 * kp) * kQKVW + voff + wb;
        const uint32_t* v0l = Ql + rowbase + (size_t)(kt + 2 * kp) * kQKVW + voff + wb;
        pV[0] = *(const uint4*)v0h;
        pV[1] = *(const uint4*)(v0h + kQKVW);
        pV[2] = *(const uint4*)v0l;
        pV[3] = *(const uint4*)(v0l + kQKVW);
    };
    auto sts_tile = [&](int buf) {
        uint32_t* KHs = ST + buf * AT_STAGE;
        uint32_t* KLs = KHs + AT_KV;
        uint32_t* VHs = KLs + AT_KV;
        uint32_t* VLs = VHs + AT_KV;
        #pragma unroll
        for (int i = 0; i < 2; i++) {
            int r = kr + 32 * i;
            *(uint4*)(KHs + r * QSTR + kw4) = pKh[i];
            *(uint4*)(KLs + r * QSTR + kw4) = pKl[i];
        }
        const uint32_t vh0[4] = {pV[0].x, pV[0].y, pV[0].z, pV[0].w};
        const uint32_t vh1[4] = {pV[1].x, pV[1].y, pV[1].z, pV[1].w};
        const uint32_t vl0[4] = {pV[2].x, pV[2].y, pV[2].z, pV[2].w};
        const uint32_t vl1[4] = {pV[3].x, pV[3].y, pV[3].z, pV[3].w};
        #pragma unroll
        for (int j = 0; j < 4; j++) {
            int hd = 2 * (wb + j);
            VHs[hd * QSTR + kp]       = prmt(vh0[j], vh1[j], 0x5410);
            VHs[(hd + 1) * QSTR + kp] = prmt(vh0[j], vh1[j], 0x7632);
            VLs[hd * QSTR + kp]       = prmt(vl0[j], vl1[j], 0x5410);
            VLs[(hd + 1) * QSTR + kp] = prmt(vl0[j], vl1[j], 0x7632);
        }
    };

    ldg_tile(0);
    sts_tile(0);
    __syncthreads();

    for (int tI = 0; tI < kS / 64; tI++) {
        if (tI + 1 < kS / 64) ldg_tile((tI + 1) * 64);

        // smem byte base of this stage
        const uint32_t stb = sb + (uint32_t)(((2 * AT_Q) + (tI & 1) * AT_STAGE) << 2);
        const uint32_t kvb = (uint32_t)(AT_KV << 2);

        // ---- S = qH kH + qL kH + qH kL ----
        float s[8][4];
        #pragma unroll
        for (int nf = 0; nf < 8; nf++) {
            s[nf][0] = s[nf][1] = s[nf][2] = s[nf][3] = 0.f;
        }
        #pragma unroll
        for (int ks = 0; ks < 4; ks++) {
            const int k0 = ks * 8;
            #pragma unroll
            for (int np = 0; np < 4; np++) {
                uint32_t roff = (uint32_t)(((np * 16 + b_row) * QSTR + k0 + b_wof) << 2);
                uint32_t kh[4], kl[4];
                ldsm_x4(kh[0], kh[1], kh[2], kh[3], stb + roff);
                ldsm_x4(kl[0], kl[1], kl[2], kl[3], stb + kvb + roff);
                #pragma unroll
                for (int half = 0; half < 2; half++) {
                    const int nf = np * 2 + half;
                    mma_bf16(s[nf], qHf[ks], kh + 2 * half);
                    mma_bf16(s[nf], qLf[ks], kh + 2 * half);
                    mma_bf16(s[nf], qHf[ks], kl + 2 * half);
                }
            }
        }

        // ---- exp + row-sum + pack P (hi/lo split) ----
        #pragma unroll
        for (int nf = 0; nf < 8; nf++) {
            float p0 = __expf(s[nf][0]);
            float p1 = __expf(s[nf][1]);
            float p2 = __expf(s[nf][2]);
            float p3 = __expf(s[nf][3]);
            s[nf][0] = p0; s[nf][1] = p1; s[nf][2] = p2; s[nf][3] = p3;
            lsum0 += p0 + p1;
            lsum1 += p2 + p3;
        }
        uint32_t pah[4][4], pal[4][4];
        #pragma unroll
        for (int kc = 0; kc < 4; kc++) {
            bf16x2_split(s[2*kc][0],   s[2*kc][1],   pah[kc][0], pal[kc][0]);
            bf16x2_split(s[2*kc][2],   s[2*kc][3],   pah[kc][1], pal[kc][1]);
            bf16x2_split(s[2*kc+1][0], s[2*kc+1][1], pah[kc][2], pal[kc][2]);
            bf16x2_split(s[2*kc+1][2], s[2*kc+1][3], pah[kc][3], pal[kc][3]);
        }

        // ---- O += pH vH + pL vH + pH vL ----
        #pragma unroll
        for (int kc = 0; kc < 4; kc++) {
            const int k0 = kc * 8;
            #pragma unroll
            for (int np = 0; np < 4; np++) {
                uint32_t roff = (uint32_t)(((np * 16 + b_row) * QSTR + k0 + b_wof) << 2);
                uint32_t vh[4], vl[4];
                ldsm_x4(vh[0], vh[1], vh[2], vh[3], stb + 2 * kvb + roff);
                ldsm_x4(vl[0], vl[1], vl[2], vl[3], stb + 3 * kvb + roff);
                #pragma unroll
                for (int half = 0; half < 2; half++) {
                    const int nf = np * 2 + half;
                    mma_bf16(o[nf], pah[kc], vh + 2 * half);
                    mma_bf16(o[nf], pal[kc], vh + 2 * half);
                    mma_bf16(o[nf], pah[kc], vl + 2 * half);
                }
            }
        }

        if (tI + 1 < kS / 64) sts_tile((tI + 1) & 1);
        __syncthreads();
    }

    // ---- reduce, normalize, split-pack, store ctx ----
    lsum0 += __shfl_xor_sync(0xFFFFFFFFu, lsum0, 1);
    lsum0 += __shfl_xor_sync(0xFFFFFFFFu, lsum0, 2);
    lsum1 += __shfl_xor_sync(0xFFFFFFFFu, lsum1, 1);
    lsum1 += __shfl_xor_sync(0xFFFFFFFFu, lsum1, 2);
    const float inv0 = 1.f / lsum0;
    const float inv1 = 1.f / lsum1;

    const size_t row0 = (size_t)(b * kS + q0 + w * 16 + g);
    #pragma unroll
    for (int nf = 0; nf < 8; nf++) {
        const int cw = h * 32 + nf * 4 + t;
        uint32_t hw, lw;
        bf16x2_split(o[nf][0] * inv0, o[nf][1] * inv0, hw, lw);
        Oh[row0 * kRW + cw] = hw;
        Ol[row0 * kRW + cw] = lw;
        bf16x2_split(o[nf][2] * inv1, o[nf][3] * inv1, hw, lw);
        Oh[(row0 + 8) * kRW + cw] = hw;
        Ol[(row0 + 8) * kRW + cw] = lw;
    }
}

// ===========================================================================
// launch
// ===========================================================================
extern "C" void kernel_launch(void* const* d_in, const int* in_sizes, int n_in,
                              void* d_out, int out_size)
{
    const float* x  = (const float*)d_in[0];
    const float* Wq = (const float*)d_in[1];
    const float* bq = (const float*)d_in[2];
    const float* Wk = (const float*)d_in[3];
    const float* bk = (const float*)d_in[4];
    const float* Wv = (const float*)d_in[5];
    const float* bv = (const float*)d_in[6];
    const float* Wo = (const float*)d_in[7];
    const float* bo = (const float*)d_in[8];
    float* out = (float*)d_out;

    uint32_t *xs_hi, *xs_lo, *wall_hi, *wall_lo, *wo_hi, *wo_lo;
    uint32_t *qkv_hi, *qkv_lo, *ctx_hi, *ctx_lo;
    float* bias_all;
    cudaGetSymbolAddress((void**)&xs_hi,   g_xs_hi);
    cudaGetSymbolAddress((void**)&xs_lo,   g_xs_lo);
    cudaGetSymbolAddress((void**)&wall_hi, g_wall_hi);
    cudaGetSymbolAddress((void**)&wall_lo, g_wall_lo);
    cudaGetSymbolAddress((void**)&wo_hi,   g_wo_hi);
    cudaGetSymbolAddress((void**)&wo_lo,   g_wo_lo);
    cudaGetSymbolAddress((void**)&bias_all,g_bias_all);
    cudaGetSymbolAddress((void**)&qkv_hi,  g_qkv_hi);
    cudaGetSymbolAddress((void**)&qkv_lo,  g_qkv_lo);
    cudaGetSymbolAddress((void**)&ctx_hi,  g_ctx_hi);
    cudaGetSymbolAddress((void**)&ctx_lo,  g_ctx_lo);

    cudaFuncSetAttribute(gemm_bf16x3,
                         cudaFuncAttributeMaxDynamicSharedMemorySize, GEMM_SMEM);
    cudaFuncSetAttribute(attn_bf16,
                         cudaFuncAttributeMaxDynamicSharedMemorySize, ATTN_SMEM);

    const int wq4 = kHID * kD / 4;   // 262144
    split_kernel<<<kM * kD / 4 / 256, 256>>>(x, xs_hi, xs_lo, kM * kD / 4);
    split_kernel<<<wq4 / 256, 256>>>(Wq, wall_hi,                      wall_lo,                      wq4);
    split_kernel<<<wq4 / 256, 256>>>(Wk, wall_hi + (size_t)kHID * kRW, wall_lo + (size_t)kHID * kRW, wq4);
    split_kernel<<<wq4 / 256, 256>>>(Wv, wall_hi + (size_t)2 * kHID * kRW, wall_lo + (size_t)2 * kHID * kRW, wq4);
    split_kernel<<<wq4 / 256, 256>>>(Wo, wo_hi, wo_lo, wq4);
    copyf_kernel<<<4, 256>>>(bq, bias_all,            kHID);
    copyf_kernel<<<4, 256>>>(bk, bias_all + kHID,     kHID);
    copyf_kernel<<<4, 256>>>(bv, bias_all + 2 * kHID, kHID);

    // fused QKV projection (3-term): M=4096, N=3072, Q scaled by 1/32
    dim3 gqkv(3 * kHID / 128, kM / 128);   // (24, 32)
    gemm_bf16x3<<<gqkv, 256, GEMM_SMEM>>>(
        xs_hi, xs_lo, wall_hi, wall_lo, bias_all,
        nullptr, qkv_hi, qkv_lo, kM, 3 * kHID, kD, kHID, kScale);

    dim3 ga(kS / 128, kB * kH);            // (16, 32)
    attn_bf16<<<ga, 256, ATTN_SMEM>>>(qkv_hi, qkv_lo, ctx_hi, ctx_lo);

    // output projection (3-term)
    dim3 go(kD / 128, kM / 128);           // (8, 32)
    gemm_bf16x3<<<go, 256, GEMM_SMEM>>>(
        ctx_hi, ctx_lo, wo_hi, wo_lo, bo,
        out, nullptr, nullptr, kM, kD, kHID, 0, 1.0f);
}

// round 9
// speedup vs baseline: 3.1359x; 1.0521x over previous
#include <cuda_runtime.h>
#include <cuda_bf16.h>
#include <cstdint>
#include <cstddef>

// ===========================================================================
// Problem constants
// ===========================================================================
constexpr int kB   = 2;
constexpr int kS   = 2048;
constexpr int kD   = 1024;
constexpr int kHID = 1024;
constexpr int kH   = 16;
constexpr int kHD  = 64;
constexpr int kM   = kB * kS;      // 4096
constexpr float kScale = 0.03125f; // 1/sqrt(1024), exact power of two

constexpr int kRW   = kD / 2;      // 512 words per row (K=1024 packed)
constexpr int kQKVW = 3 * kRW;     // 1536 words per qkv row

// ===========================================================================
// Scratch (device globals; allocation-free rule)
// ===========================================================================
__device__ uint32_t g_xs_hi [(size_t)kM * kRW];
__device__ uint32_t g_xs_lo [(size_t)kM * kRW];
__device__ uint32_t g_wall_hi[(size_t)3 * kHID * kRW];
__device__ uint32_t g_wall_lo[(size_t)3 * kHID * kRW];
__device__ uint32_t g_wo_hi [(size_t)kD * kRW];
__device__ uint32_t g_wo_lo [(size_t)kD * kRW];
__device__ float    g_bias_all[3 * kHID];
__device__ uint32_t g_qkv_hi[(size_t)kM * kQKVW];
__device__ uint32_t g_qkv_lo[(size_t)kM * kQKVW];
__device__ uint32_t g_ctx_hi[(size_t)kM * kRW];
__device__ uint32_t g_ctx_lo[(size_t)kM * kRW];

// ===========================================================================
// helpers
// ===========================================================================
__device__ __forceinline__ void mma_bf16(float* d, const uint32_t* a, const uint32_t* b) {
    asm volatile(
        "mma.sync.aligned.m16n8k16.row.col.f32.bf16.bf16.f32 "
        "{%0,%1,%2,%3}, {%4,%5,%6,%7}, {%8,%9}, {%0,%1,%2,%3};"
        : "+f"(d[0]), "+f"(d[1]), "+f"(d[2]), "+f"(d[3])
        : "r"(a[0]), "r"(a[1]), "r"(a[2]), "r"(a[3]),
          "r"(b[0]), "r"(b[1]));
}

__device__ __forceinline__ void ldsm_x4(uint32_t& r0, uint32_t& r1,
                                        uint32_t& r2, uint32_t& r3, uint32_t addr) {
    asm volatile(
        "ldmatrix.sync.aligned.m8n8.x4.shared.b16 {%0,%1,%2,%3}, [%4];"
        : "=r"(r0), "=r"(r1), "=r"(r2), "=r"(r3) : "r"(addr));
}

__device__ __forceinline__ uint32_t smem_u32(const void* p) {
    uint32_t a;
    asm("{ .reg .u64 t; cvta.to.shared.u64 t, %1; cvt.u32.u64 %0, t; }"
        : "=r"(a) : "l"(p));
    return a;
}

__device__ __forceinline__ void cp_async16(uint32_t smem_addr, const void* gmem) {
    asm volatile("cp.async.cg.shared.global [%0], [%1], 16;"
                 :: "r"(smem_addr), "l"(gmem));
}
__device__ __forceinline__ void cp_commit() {
    asm volatile("cp.async.commit_group;");
}
__device__ __forceinline__ void cp_wait0() {
    asm volatile("cp.async.wait_group 0;");
}

// pack two floats into bf16x2 word (x0 -> low) + residual word
__device__ __forceinline__ void bf16x2_split(float x0, float x1,
                                             uint32_t& hi, uint32_t& lo) {
    __nv_bfloat16 h0 = __float2bfloat16_rn(x0);
    __nv_bfloat16 h1 = __float2bfloat16_rn(x1);
    float r0 = x0 - __bfloat162float(h0);
    float r1 = x1 - __bfloat162float(h1);
    __nv_bfloat16 l0 = __float2bfloat16_rn(r0);
    __nv_bfloat16 l1 = __float2bfloat16_rn(r1);
    hi = ((uint32_t)__bfloat16_as_ushort(h1) << 16) | __bfloat16_as_ushort(h0);
    lo = ((uint32_t)__bfloat16_as_ushort(l1) << 16) | __bfloat16_as_ushort(l0);
}

__device__ __forceinline__ uint32_t prmt(uint32_t a, uint32_t b, uint32_t sel) {
    uint32_t d;
    asm("prmt.b32 %0, %1, %2, %3;" : "=r"(d) : "r"(a), "r"(b), "r"(sel));
    return d;
}

// ===========================================================================
// split kernels
// ===========================================================================
__global__ void split_kernel(const float* __restrict__ src,
                             uint32_t* __restrict__ hi,
                             uint32_t* __restrict__ lo, int n4)
{
    int i = blockIdx.x * blockDim.x + threadIdx.x;
    if (i >= n4) return;
    float4 v = ((const float4*)src)[i];
    uint32_t h0, l0, h1, l1;
    bf16x2_split(v.x, v.y, h0, l0);
    bf16x2_split(v.z, v.w, h1, l1);
    ((uint2*)hi)[i] = make_uint2(h0, h1);
    ((uint2*)lo)[i] = make_uint2(l0, l1);
}

// fused split of the 4 weight matrices (regions 0..2 -> wall, 3 -> wo)
__global__ void split_w4_kernel(const float* __restrict__ Wq,
                                const float* __restrict__ Wk,
                                const float* __restrict__ Wv,
                                const float* __restrict__ Wo,
                                uint32_t* __restrict__ wall_hi,
                                uint32_t* __restrict__ wall_lo,
                                uint32_t* __restrict__ wo_hi,
                                uint32_t* __restrict__ wo_lo,
                                int n4region)
{
    int gi = blockIdx.x * blockDim.x + threadIdx.x;
    int region = gi / n4region;
    int i = gi - region * n4region;
    const float* src = (region == 0) ? Wq : (region == 1) ? Wk
                     : (region == 2) ? Wv : Wo;
    uint32_t* hi = (region < 3) ? wall_hi + (size_t)region * 2 * n4region : wo_hi;
    uint32_t* lo = (region < 3) ? wall_lo + (size_t)region * 2 * n4region : wo_lo;
    float4 v = ((const float4*)src)[i];
    uint32_t h0, l0, h1, l1;
    bf16x2_split(v.x, v.y, h0, l0);
    bf16x2_split(v.z, v.w, h1, l1);
    ((uint2*)hi)[i] = make_uint2(h0, h1);
    ((uint2*)lo)[i] = make_uint2(l0, l1);
}

__global__ void bias3_kernel(const float* __restrict__ bq,
                             const float* __restrict__ bk,
                             const float* __restrict__ bv,
                             float* __restrict__ dst)
{
    int i = blockIdx.x * blockDim.x + threadIdx.x;
    if (i < kHID)              dst[i] = bq[i];
    else if (i < 2 * kHID)     dst[i] = bk[i - kHID];
    else if (i < 3 * kHID)     dst[i] = bv[i - 2 * kHID];
}

// ===========================================================================
// bf16x3 GEMM: C[M,N] = A[M,K] @ B[N,K]^T + bias
// cp.async 2-stage staging; 2 CTAs/SM. Fragment loads via ldmatrix.x4.
// CTA 128x128, BK=32 elems (16 words), 8 warps (4x2), warp 32x64.
// ===========================================================================
constexpr int GW    = 16;              // words per row per chunk
constexpr int GSTR  = 20;              // padded word stride
constexpr int GT    = 128 * GSTR;      // words per tile array (2560)
constexpr int GSTAGE = 4 * GT;
constexpr int GEMM_SMEM = 2 * GSTAGE * 4;   // 81920 B

__global__ __launch_bounds__(256, 2)
void gemm_bf16x3(const uint32_t* __restrict__ Ah, const uint32_t* __restrict__ Al,
                 const uint32_t* __restrict__ Bh, const uint32_t* __restrict__ Bl,
                 const float* __restrict__ bias,
                 float* __restrict__ Cf,
                 uint32_t* __restrict__ Ch, uint32_t* __restrict__ Cl,
                 int M, int N, int K, int scaleCols, float scaleVal)
{
    extern __shared__ uint32_t smw[];
    const uint32_t sb = smem_u32(smw);

    const int tid  = threadIdx.x;
    const int wid  = tid >> 5;
    const int lane = tid & 31;
    const int g    = lane >> 2;
    const int t    = lane & 3;

    const int wm = (wid & 3) * 32;
    const int wn = (wid >> 2) * 64;

    // ldmatrix lane constants
    const int lm8 = lane & 7;
    const int lq  = lane >> 3;
    const int a_row = lm8 + (lq & 1) * 8;
    const int a_wof = (lq >> 1) * 4;
    const int b_row = lm8 + (lq >> 1) * 8;
    const int b_wof = (lq & 1) * 4;

    const int brow = blockIdx.y * 128;
    const int bcol = blockIdx.x * 128;
    const int kw   = K >> 1;
    const int nchunks = K / 32;

    const int lr0 = tid >> 2;            // row 0..63 (+64 for second)
    const int lw4 = (tid & 3) * 4;

    float acc[2][8][4];
    #pragma unroll
    for (int mi = 0; mi < 2; mi++)
        #pragma unroll
        for (int nf = 0; nf < 8; nf++)
            #pragma unroll
            for (int j = 0; j < 4; j++) acc[mi][nf][j] = 0.f;

    // cp.async staging of chunk c into buffer buf
    auto cpa_chunk = [&](int c, int buf) {
        const uint32_t s = sb + (uint32_t)((buf * GSTAGE) << 2);
        const uint32_t* a_h = Ah + (size_t)brow * kw + c * GW + lw4;
        const uint32_t* a_l = Al + (size_t)brow * kw + c * GW + lw4;
        const uint32_t* b_h = Bh + (size_t)bcol * kw + c * GW + lw4;
        const uint32_t* b_l = Bl + (size_t)bcol * kw + c * GW + lw4;
        #pragma unroll
        for (int j = 0; j < 2; j++) {
            const int r = lr0 + 64 * j;
            const uint32_t d = (uint32_t)((r * GSTR + lw4) << 2);
            cp_async16(s + ((0 * GT) << 2) + d, a_h + (size_t)r * kw);
            cp_async16(s + ((1 * GT) << 2) + d, a_l + (size_t)r * kw);
            cp_async16(s + ((2 * GT) << 2) + d, b_h + (size_t)r * kw);
            cp_async16(s + ((3 * GT) << 2) + d, b_l + (size_t)r * kw);
        }
        cp_commit();
    };

    cpa_chunk(0, 0);

    for (int c = 0; c < nchunks; c++) {
        cp_wait0();
        __syncthreads();
        if (c + 1 < nchunks) cpa_chunk(c + 1, (c + 1) & 1);

        const uint32_t base = sb + (uint32_t)(((c & 1) * GSTAGE) << 2);

        #pragma unroll
        for (int kk = 0; kk < 2; kk++) {
            const int k0 = kk * 8;
            uint32_t aH[2][4], aL[2][4];
            #pragma unroll
            for (int mi = 0; mi < 2; mi++) {
                uint32_t arow = (uint32_t)((wm + mi * 16 + a_row) * GSTR + k0 + a_wof);
                ldsm_x4(aH[mi][0], aH[mi][1], aH[mi][2], aH[mi][3],
                        base + ((0 * GT + arow) << 2));
                ldsm_x4(aL[mi][0], aL[mi][1], aL[mi][2], aL[mi][3],
                        base + ((1 * GT + arow) << 2));
            }
            #pragma unroll
            for (int np = 0; np < 4; np++) {
                uint32_t nrow = (uint32_t)((wn + np * 16 + b_row) * GSTR + k0 + b_wof);
                uint32_t bh[4], bl[4];
                ldsm_x4(bh[0], bh[1], bh[2], bh[3], base + ((2 * GT + nrow) << 2));
                ldsm_x4(bl[0], bl[1], bl[2], bl[3], base + ((3 * GT + nrow) << 2));
                #pragma unroll
                for (int half = 0; half < 2; half++) {
                    const int nf = np * 2 + half;
                    #pragma unroll
                    for (int mi = 0; mi < 2; mi++) {
                        mma_bf16(acc[mi][nf], aH[mi], bh + 2 * half);
                        mma_bf16(acc[mi][nf], aH[mi], bl + 2 * half);
                        mma_bf16(acc[mi][nf], aL[mi], bh + 2 * half);
                    }
                }
            }
        }
    }

    // epilogue
    const int nw = N >> 1;
    #pragma unroll
    for (int mi = 0; mi < 2; mi++) {
        const int r0 = brow + wm + mi * 16 + g;
        #pragma unroll
        for (int nf = 0; nf < 8; nf++) {
            const int c0 = bcol + wn + nf * 8 + 2 * t;
            float bx = bias[c0], by = bias[c0 + 1];
            float v0 = acc[mi][nf][0] + bx, v1 = acc[mi][nf][1] + by;
            float v2 = acc[mi][nf][2] + bx, v3 = acc[mi][nf][3] + by;
            if (Cf) {
                *(float2*)(Cf + (size_t)r0 * N + c0)       = make_float2(v0, v1);
                *(float2*)(Cf + (size_t)(r0 + 8) * N + c0) = make_float2(v2, v3);
            } else {
                float sc = (c0 < scaleCols) ? scaleVal : 1.0f;
                v0 *= sc; v1 *= sc; v2 *= sc; v3 *= sc;
                uint32_t h, l;
                bf16x2_split(v0, v1, h, l);
                Ch[(size_t)r0 * nw + (c0 >> 1)] = h;
                Cl[(size_t)r0 * nw + (c0 >> 1)] = l;
                bf16x2_split(v2, v3, h, l);
                Ch[(size_t)(r0 + 8) * nw + (c0 >> 1)] = h;
                Cl[(size_t)(r0 + 8) * nw + (c0 >> 1)] = l;
            }
        }
    }
}

// ===========================================================================
// bf16x3 flash attention (unchanged from R8).
// ===========================================================================
constexpr int QSTR = 36;                     // padded word stride
constexpr int AT_Q  = 128 * QSTR;            // per half (hi or lo)
constexpr int AT_KV = 64 * QSTR;
constexpr int AT_STAGE = 4 * AT_KV;          // KH KL VH VL
constexpr int ATTN_SMEM = (2 * AT_Q + 2 * AT_STAGE) * 4;  // 110,592 B

__global__ __launch_bounds__(256, 1)
void attn_bf16(const uint32_t* __restrict__ Qh, const uint32_t* __restrict__ Ql,
               uint32_t* __restrict__ Oh, uint32_t* __restrict__ Ol)
{
    extern __shared__ uint32_t smw[];
    uint32_t* QH = smw;
    uint32_t* QL = QH + AT_Q;
    uint32_t* ST = QL + AT_Q;   // 2 stages
    const uint32_t sb = smem_u32(smw);

    const int tid  = threadIdx.x;
    const int w    = tid >> 5;
    const int lane = tid & 31;
    const int g    = lane >> 2;
    const int t    = lane & 3;

    const int lm8 = lane & 7;
    const int lq  = lane >> 3;
    const int b_row = lm8 + (lq >> 1) * 8;
    const int b_wof = (lq & 1) * 4;

    const int bh = blockIdx.y;
    const int b  = bh >> 4;
    const int h  = bh & 15;
    const int q0 = blockIdx.x * 128;

    const size_t rowbase = (size_t)(b * kS) * kQKVW;
    const int qoff = h * 32;
    const int koff = 512 + h * 32;
    const int voff = 1024 + h * 32;

    // ---- stage Q (hi + lo words) ----
    {
        const uint32_t* qh = Qh + rowbase + (size_t)q0 * kQKVW + qoff;
        const uint32_t* ql = Ql + rowbase + (size_t)q0 * kQKVW + qoff;
        #pragma unroll
        for (int i = 0; i < 4; i++) {
            int idx = tid + 256 * i;
            int r = idx >> 3, w4 = (idx & 7) * 4;
            *(uint4*)(QH + r * QSTR + w4) = *(const uint4*)(qh + (size_t)r * kQKVW + w4);
            *(uint4*)(QL + r * QSTR + w4) = *(const uint4*)(ql + (size_t)r * kQKVW + w4);
        }
    }
    __syncthreads();

    // ---- resident Q fragments (hi + lo) ----
    uint32_t qHf[4][4], qLf[4][4];
    {
        const int r0 = (w * 16 + g) * QSTR;
        const int r1 = r0 + 8 * QSTR;
        #pragma unroll
        for (int ks = 0; ks < 4; ks++) {
            const int k0 = ks * 8;
            qHf[ks][0] = QH[r0 + k0 + t];
            qHf[ks][1] = QH[r1 + k0 + t];
            qHf[ks][2] = QH[r0 + k0 + t + 4];
            qHf[ks][3] = QH[r1 + k0 + t + 4];
            qLf[ks][0] = QL[r0 + k0 + t];
            qLf[ks][1] = QL[r1 + k0 + t];
            qLf[ks][2] = QL[r0 + k0 + t + 4];
            qLf[ks][3] = QL[r1 + k0 + t + 4];
        }
    }

    float o[8][4];
    #pragma unroll
    for (int nf = 0; nf < 8; nf++)
        #pragma unroll
        for (int e = 0; e < 4; e++) o[nf][e] = 0.f;
    float lsum0 = 0.f, lsum1 = 0.f;

    // K/V prefetch registers
    uint4 pKh[2], pKl[2], pV[4];
    const int kr  = tid >> 3;
    const int kw4 = (tid & 7) * 4;
    const int kp  = lane;               // V: key pair id
    const int wb  = w * 4;              // V: word block

    auto ldg_tile = [&](int kt) {
        const uint32_t* khp = Qh + rowbase + (size_t)kt * kQKVW + koff;
        const uint32_t* klp = Ql + rowbase + (size_t)kt * kQKVW + koff;
        #pragma unroll
        for (int i = 0; i < 2; i++) {
            int r = kr + 32 * i;
            pKh[i] = *(const uint4*)(khp + (size_t)r * kQKVW + kw4);
            pKl[i] = *(const uint4*)(klp + (size_t)r * kQKVW + kw4);
        }
        const uint32_t* v0h = Qh + rowbase + (size_t)(kt + 2 * kp) * kQKVW + voff + wb;
        const uint32_t* v0l = Ql + rowbase + (size_t)(kt + 2 * kp) * kQKVW + voff + wb;
        pV[0] = *(const uint4*)v0h;
        pV[1] = *(const uint4*)(v0h + kQKVW);
        pV[2] = *(const uint4*)v0l;
        pV[3] = *(const uint4*)(v0l + kQKVW);
    };
    auto sts_tile = [&](int buf) {
        uint32_t* KHs = ST + buf * AT_STAGE;
        uint32_t* KLs = KHs + AT_KV;
        uint32_t* VHs = KLs + AT_KV;
        uint32_t* VLs = VHs + AT_KV;
        #pragma unroll
        for (int i = 0; i < 2; i++) {
            int r = kr + 32 * i;
            *(uint4*)(KHs + r * QSTR + kw4) = pKh[i];
            *(uint4*)(KLs + r * QSTR + kw4) = pKl[i];
        }
        const uint32_t vh0[4] = {pV[0].x, pV[0].y, pV[0].z, pV[0].w};
        const uint32_t vh1[4] = {pV[1].x, pV[1].y, pV[1].z, pV[1].w};
        const uint32_t vl0[4] = {pV[2].x, pV[2].y, pV[2].z, pV[2].w};
        const uint32_t vl1[4] = {pV[3].x, pV[3].y, pV[3].z, pV[3].w};
        #pragma unroll
        for (int j = 0; j < 4; j++) {
            int hd = 2 * (wb + j);
            VHs[hd * QSTR + kp]       = prmt(vh0[j], vh1[j], 0x5410);
            VHs[(hd + 1) * QSTR + kp] = prmt(vh0[j], vh1[j], 0x7632);
            VLs[hd * QSTR + kp]       = prmt(vl0[j], vl1[j], 0x5410);
            VLs[(hd + 1) * QSTR + kp] = prmt(vl0[j], vl1[j], 0x7632);
        }
    };

    ldg_tile(0);
    sts_tile(0);
    __syncthreads();

    for (int tI = 0; tI < kS / 64; tI++) {
        if (tI + 1 < kS / 64) ldg_tile((tI + 1) * 64);

        const uint32_t stb = sb + (uint32_t)(((2 * AT_Q) + (tI & 1) * AT_STAGE) << 2);
        const uint32_t kvb = (uint32_t)(AT_KV << 2);

        // ---- S = qH kH + qL kH + qH kL ----
        float s[8][4];
        #pragma unroll
        for (int nf = 0; nf < 8; nf++) {
            s[nf][0] = s[nf][1] = s[nf][2] = s[nf][3] = 0.f;
        }
        #pragma unroll
        for (int ks = 0; ks < 4; ks++) {
            const int k0 = ks * 8;
            #pragma unroll
            for (int np = 0; np < 4; np++) {
                uint32_t roff = (uint32_t)(((np * 16 + b_row) * QSTR + k0 + b_wof) << 2);
                uint32_t kh[4], kl[4];
                ldsm_x4(kh[0], kh[1], kh[2], kh[3], stb + roff);
                ldsm_x4(kl[0], kl[1], kl[2], kl[3], stb + kvb + roff);
                #pragma unroll
                for (int half = 0; half < 2; half++) {
                    const int nf = np * 2 + half;
                    mma_bf16(s[nf], qHf[ks], kh + 2 * half);
                    mma_bf16(s[nf], qLf[ks], kh + 2 * half);
                    mma_bf16(s[nf], qHf[ks], kl + 2 * half);
                }
            }
        }

        // ---- exp + row-sum + pack P (hi/lo split) ----
        #pragma unroll
        for (int nf = 0; nf < 8; nf++) {
            float p0 = __expf(s[nf][0]);
            float p1 = __expf(s[nf][1]);
            float p2 = __expf(s[nf][2]);
            float p3 = __expf(s[nf][3]);
            s[nf][0] = p0; s[nf][1] = p1; s[nf][2] = p2; s[nf][3] = p3;
            lsum0 += p0 + p1;
            lsum1 += p2 + p3;
        }
        uint32_t pah[4][4], pal[4][4];
        #pragma unroll
        for (int kc = 0; kc < 4; kc++) {
            bf16x2_split(s[2*kc][0],   s[2*kc][1],   pah[kc][0], pal[kc][0]);
            bf16x2_split(s[2*kc][2],   s[2*kc][3],   pah[kc][1], pal[kc][1]);
            bf16x2_split(s[2*kc+1][0], s[2*kc+1][1], pah[kc][2], pal[kc][2]);
            bf16x2_split(s[2*kc+1][2], s[2*kc+1][3], pah[kc][3], pal[kc][3]);
        }

        // ---- O += pH vH + pL vH + pH vL ----
        #pragma unroll
        for (int kc = 0; kc < 4; kc++) {
            const int k0 = kc * 8;
            #pragma unroll
            for (int np = 0; np < 4; np++) {
                uint32_t roff = (uint32_t)(((np * 16 + b_row) * QSTR + k0 + b_wof) << 2);
                uint32_t vh[4], vl[4];
                ldsm_x4(vh[0], vh[1], vh[2], vh[3], stb + 2 * kvb + roff);
                ldsm_x4(vl[0], vl[1], vl[2], vl[3], stb + 3 * kvb + roff);
                #pragma unroll
                for (int half = 0; half < 2; half++) {
                    const int nf = np * 2 + half;
                    mma_bf16(o[nf], pah[kc], vh + 2 * half);
                    mma_bf16(o[nf], pal[kc], vh + 2 * half);
                    mma_bf16(o[nf], pah[kc], vl + 2 * half);
                }
            }
        }

        if (tI + 1 < kS / 64) sts_tile((tI + 1) & 1);
        __syncthreads();
    }

    // ---- reduce, normalize, split-pack, store ctx ----
    lsum0 += __shfl_xor_sync(0xFFFFFFFFu, lsum0, 1);
    lsum0 += __shfl_xor_sync(0xFFFFFFFFu, lsum0, 2);
    lsum1 += __shfl_xor_sync(0xFFFFFFFFu, lsum1, 1);
    lsum1 += __shfl_xor_sync(0xFFFFFFFFu, lsum1, 2);
    const float inv0 = 1.f / lsum0;
    const float inv1 = 1.f / lsum1;

    const size_t row0 = (size_t)(b * kS + q0 + w * 16 + g);
    #pragma unroll
    for (int nf = 0; nf < 8; nf++) {
        const int cw = h * 32 + nf * 4 + t;
        uint32_t hw, lw;
        bf16x2_split(o[nf][0] * inv0, o[nf][1] * inv0, hw, lw);
        Oh[row0 * kRW + cw] = hw;
        Ol[row0 * kRW + cw] = lw;
        bf16x2_split(o[nf][2] * inv1, o[nf][3] * inv1, hw, lw);
        Oh[(row0 + 8) * kRW + cw] = hw;
        Ol[(row0 + 8) * kRW + cw] = lw;
    }
}

// ===========================================================================
// launch
// ===========================================================================
extern "C" void kernel_launch(void* const* d_in, const int* in_sizes, int n_in,
                              void* d_out, int out_size)
{
    const float* x  = (const float*)d_in[0];
    const float* Wq = (const float*)d_in[1];
    const float* bq = (const float*)d_in[2];
    const float* Wk = (const float*)d_in[3];
    const float* bk = (const float*)d_in[4];
    const float* Wv = (const float*)d_in[5];
    const float* bv = (const float*)d_in[6];
    const float* Wo = (const float*)d_in[7];
    const float* bo = (const float*)d_in[8];
    float* out = (float*)d_out;

    uint32_t *xs_hi, *xs_lo, *wall_hi, *wall_lo, *wo_hi, *wo_lo;
    uint32_t *qkv_hi, *qkv_lo, *ctx_hi, *ctx_lo;
    float* bias_all;
    cudaGetSymbolAddress((void**)&xs_hi,   g_xs_hi);
    cudaGetSymbolAddress((void**)&xs_lo,   g_xs_lo);
    cudaGetSymbolAddress((void**)&wall_hi, g_wall_hi);
    cudaGetSymbolAddress((void**)&wall_lo, g_wall_lo);
    cudaGetSymbolAddress((void**)&wo_hi,   g_wo_hi);
    cudaGetSymbolAddress((void**)&wo_lo,   g_wo_lo);
    cudaGetSymbolAddress((void**)&bias_all,g_bias_all);
    cudaGetSymbolAddress((void**)&qkv_hi,  g_qkv_hi);
    cudaGetSymbolAddress((void**)&qkv_lo,  g_qkv_lo);
    cudaGetSymbolAddress((void**)&ctx_hi,  g_ctx_hi);
    cudaGetSymbolAddress((void**)&ctx_lo,  g_ctx_lo);

    cudaFuncSetAttribute(gemm_bf16x3,
                         cudaFuncAttributeMaxDynamicSharedMemorySize, GEMM_SMEM);
    cudaFuncSetAttribute(attn_bf16,
                         cudaFuncAttributeMaxDynamicSharedMemorySize, ATTN_SMEM);

    const int wq4 = kHID * kD / 4;   // 262144
    split_kernel<<<kM * kD / 4 / 256, 256>>>(x, xs_hi, xs_lo, kM * kD / 4);
    split_w4_kernel<<<4 * wq4 / 256, 256>>>(Wq, Wk, Wv, Wo,
                                            wall_hi, wall_lo, wo_hi, wo_lo, wq4);
    bias3_kernel<<<12, 256>>>(bq, bk, bv, bias_all);

    // fused QKV projection (3-term): M=4096, N=3072, Q scaled by 1/32
    dim3 gqkv(3 * kHID / 128, kM / 128);   // (24, 32)
    gemm_bf16x3<<<gqkv, 256, GEMM_SMEM>>>(
        xs_hi, xs_lo, wall_hi, wall_lo, bias_all,
        nullptr, qkv_hi, qkv_lo, kM, 3 * kHID, kD, kHID, kScale);

    dim3 ga(kS / 128, kB * kH);            // (16, 32)
    attn_bf16<<<ga, 256, ATTN_SMEM>>>(qkv_hi, qkv_lo, ctx_hi, ctx_lo);

    // output projection (3-term)
    dim3 go(kD / 128, kM / 128);           // (8, 32)
    gemm_bf16x3<<<go, 256, GEMM_SMEM>>>(
        ctx_hi, ctx_lo, wo_hi, wo_lo, bo,
        out, nullptr, nullptr, kM, kD, kHID, 0, 1.0f);
}

// round 10
// speedup vs baseline: 3.2530x; 1.0373x over previous
#include <cuda_runtime.h>
#include <cuda_bf16.h>
#include <cstdint>
#include <cstddef>

// ===========================================================================
// Problem constants
// ===========================================================================
constexpr int kB   = 2;
constexpr int kS   = 2048;
constexpr int kD   = 1024;
constexpr int kHID = 1024;
constexpr int kH   = 16;
constexpr int kHD  = 64;
constexpr int kM   = kB * kS;      // 4096
constexpr float kScale = 0.03125f; // 1/sqrt(1024), exact power of two

constexpr int kRW   = kD / 2;      // 512 words per row (K=1024 packed)
constexpr int kQKVW = 3 * kRW;     // 1536 words per qkv row

// ===========================================================================
// Scratch (device globals; allocation-free rule)
// ===========================================================================
__device__ uint32_t g_xs_hi [(size_t)kM * kRW];
__device__ uint32_t g_xs_lo [(size_t)kM * kRW];
__device__ uint32_t g_wall_hi[(size_t)3 * kHID * kRW];
__device__ uint32_t g_wall_lo[(size_t)3 * kHID * kRW];
__device__ uint32_t g_wo_hi [(size_t)kD * kRW];
__device__ uint32_t g_wo_lo [(size_t)kD * kRW];
__device__ float    g_bias_all[3 * kHID];
__device__ uint32_t g_qkv_hi[(size_t)kM * kQKVW];
__device__ uint32_t g_qkv_lo[(size_t)kM * kQKVW];
__device__ uint32_t g_ctx_hi[(size_t)kM * kRW];
__device__ uint32_t g_ctx_lo[(size_t)kM * kRW];

// ===========================================================================
// helpers
// ===========================================================================
__device__ __forceinline__ void mma_bf16(float* d, const uint32_t* a, const uint32_t* b) {
    asm volatile(
        "mma.sync.aligned.m16n8k16.row.col.f32.bf16.bf16.f32 "
        "{%0,%1,%2,%3}, {%4,%5,%6,%7}, {%8,%9}, {%0,%1,%2,%3};"
        : "+f"(d[0]), "+f"(d[1]), "+f"(d[2]), "+f"(d[3])
        : "r"(a[0]), "r"(a[1]), "r"(a[2]), "r"(a[3]),
          "r"(b[0]), "r"(b[1]));
}

__device__ __forceinline__ void ldsm_x4(uint32_t& r0, uint32_t& r1,
                                        uint32_t& r2, uint32_t& r3, uint32_t addr) {
    asm volatile(
        "ldmatrix.sync.aligned.m8n8.x4.shared.b16 {%0,%1,%2,%3}, [%4];"
        : "=r"(r0), "=r"(r1), "=r"(r2), "=r"(r3) : "r"(addr));
}

__device__ __forceinline__ void ldsm_x4_t(uint32_t& r0, uint32_t& r1,
                                          uint32_t& r2, uint32_t& r3, uint32_t addr) {
    asm volatile(
        "ldmatrix.sync.aligned.m8n8.x4.trans.shared.b16 {%0,%1,%2,%3}, [%4];"
        : "=r"(r0), "=r"(r1), "=r"(r2), "=r"(r3) : "r"(addr));
}

__device__ __forceinline__ uint32_t smem_u32(const void* p) {
    uint32_t a;
    asm("{ .reg .u64 t; cvta.to.shared.u64 t, %1; cvt.u32.u64 %0, t; }"
        : "=r"(a) : "l"(p));
    return a;
}

__device__ __forceinline__ void cp_async16(uint32_t smem_addr, const void* gmem) {
    asm volatile("cp.async.cg.shared.global [%0], [%1], 16;"
                 :: "r"(smem_addr), "l"(gmem));
}
__device__ __forceinline__ void cp_commit() {
    asm volatile("cp.async.commit_group;");
}
__device__ __forceinline__ void cp_wait0() {
    asm volatile("cp.async.wait_group 0;");
}

// pack two floats into bf16x2 word (x0 -> low) + residual word
__device__ __forceinline__ void bf16x2_split(float x0, float x1,
                                             uint32_t& hi, uint32_t& lo) {
    __nv_bfloat16 h0 = __float2bfloat16_rn(x0);
    __nv_bfloat16 h1 = __float2bfloat16_rn(x1);
    float r0 = x0 - __bfloat162float(h0);
    float r1 = x1 - __bfloat162float(h1);
    __nv_bfloat16 l0 = __float2bfloat16_rn(r0);
    __nv_bfloat16 l1 = __float2bfloat16_rn(r1);
    hi = ((uint32_t)__bfloat16_as_ushort(h1) << 16) | __bfloat16_as_ushort(h0);
    lo = ((uint32_t)__bfloat16_as_ushort(l1) << 16) | __bfloat16_as_ushort(l0);
}

// ===========================================================================
// split kernels
// ===========================================================================
__global__ void split_kernel(const float* __restrict__ src,
                             uint32_t* __restrict__ hi,
                             uint32_t* __restrict__ lo, int n4)
{
    int i = blockIdx.x * blockDim.x + threadIdx.x;
    if (i >= n4) return;
    float4 v = ((const float4*)src)[i];
    uint32_t h0, l0, h1, l1;
    bf16x2_split(v.x, v.y, h0, l0);
    bf16x2_split(v.z, v.w, h1, l1);
    ((uint2*)hi)[i] = make_uint2(h0, h1);
    ((uint2*)lo)[i] = make_uint2(l0, l1);
}

// fused split of the 4 weight matrices (regions 0..2 -> wall, 3 -> wo)
__global__ void split_w4_kernel(const float* __restrict__ Wq,
                                const float* __restrict__ Wk,
                                const float* __restrict__ Wv,
                                const float* __restrict__ Wo,
                                uint32_t* __restrict__ wall_hi,
                                uint32_t* __restrict__ wall_lo,
                                uint32_t* __restrict__ wo_hi,
                                uint32_t* __restrict__ wo_lo,
                                int n4region)
{
    int gi = blockIdx.x * blockDim.x + threadIdx.x;
    int region = gi / n4region;
    int i = gi - region * n4region;
    const float* src = (region == 0) ? Wq : (region == 1) ? Wk
                     : (region == 2) ? Wv : Wo;
    uint32_t* hi = (region < 3) ? wall_hi + (size_t)region * 2 * n4region : wo_hi;
    uint32_t* lo = (region < 3) ? wall_lo + (size_t)region * 2 * n4region : wo_lo;
    float4 v = ((const float4*)src)[i];
    uint32_t h0, l0, h1, l1;
    bf16x2_split(v.x, v.y, h0, l0);
    bf16x2_split(v.z, v.w, h1, l1);
    ((uint2*)hi)[i] = make_uint2(h0, h1);
    ((uint2*)lo)[i] = make_uint2(l0, l1);
}

__global__ void bias3_kernel(const float* __restrict__ bq,
                             const float* __restrict__ bk,
                             const float* __restrict__ bv,
                             float* __restrict__ dst)
{
    int i = blockIdx.x * blockDim.x + threadIdx.x;
    if (i < kHID)              dst[i] = bq[i];
    else if (i < 2 * kHID)     dst[i] = bk[i - kHID];
    else if (i < 3 * kHID)     dst[i] = bv[i - 2 * kHID];
}

// ===========================================================================
// bf16x3 GEMM (unchanged from R9): cp.async 2-stage, 2 CTAs/SM, ldmatrix.
// ===========================================================================
constexpr int GW    = 16;
constexpr int GSTR  = 20;
constexpr int GT    = 128 * GSTR;
constexpr int GSTAGE = 4 * GT;
constexpr int GEMM_SMEM = 2 * GSTAGE * 4;   // 81920 B

__global__ __launch_bounds__(256, 2)
void gemm_bf16x3(const uint32_t* __restrict__ Ah, const uint32_t* __restrict__ Al,
                 const uint32_t* __restrict__ Bh, const uint32_t* __restrict__ Bl,
                 const float* __restrict__ bias,
                 float* __restrict__ Cf,
                 uint32_t* __restrict__ Ch, uint32_t* __restrict__ Cl,
                 int M, int N, int K, int scaleCols, float scaleVal)
{
    extern __shared__ uint32_t smw[];
    const uint32_t sb = smem_u32(smw);

    const int tid  = threadIdx.x;
    const int wid  = tid >> 5;
    const int lane = tid & 31;
    const int g    = lane >> 2;
    const int t    = lane & 3;

    const int wm = (wid & 3) * 32;
    const int wn = (wid >> 2) * 64;

    const int lm8 = lane & 7;
    const int lq  = lane >> 3;
    const int a_row = lm8 + (lq & 1) * 8;
    const int a_wof = (lq >> 1) * 4;
    const int b_row = lm8 + (lq >> 1) * 8;
    const int b_wof = (lq & 1) * 4;

    const int brow = blockIdx.y * 128;
    const int bcol = blockIdx.x * 128;
    const int kw   = K >> 1;
    const int nchunks = K / 32;

    const int lr0 = tid >> 2;
    const int lw4 = (tid & 3) * 4;

    float acc[2][8][4];
    #pragma unroll
    for (int mi = 0; mi < 2; mi++)
        #pragma unroll
        for (int nf = 0; nf < 8; nf++)
            #pragma unroll
            for (int j = 0; j < 4; j++) acc[mi][nf][j] = 0.f;

    auto cpa_chunk = [&](int c, int buf) {
        const uint32_t s = sb + (uint32_t)((buf * GSTAGE) << 2);
        const uint32_t* a_h = Ah + (size_t)brow * kw + c * GW + lw4;
        const uint32_t* a_l = Al + (size_t)brow * kw + c * GW + lw4;
        const uint32_t* b_h = Bh + (size_t)bcol * kw + c * GW + lw4;
        const uint32_t* b_l = Bl + (size_t)bcol * kw + c * GW + lw4;
        #pragma unroll
        for (int j = 0; j < 2; j++) {
            const int r = lr0 + 64 * j;
            const uint32_t d = (uint32_t)((r * GSTR + lw4) << 2);
            cp_async16(s + ((0 * GT) << 2) + d, a_h + (size_t)r * kw);
            cp_async16(s + ((1 * GT) << 2) + d, a_l + (size_t)r * kw);
            cp_async16(s + ((2 * GT) << 2) + d, b_h + (size_t)r * kw);
            cp_async16(s + ((3 * GT) << 2) + d, b_l + (size_t)r * kw);
        }
        cp_commit();
    };

    cpa_chunk(0, 0);

    for (int c = 0; c < nchunks; c++) {
        cp_wait0();
        __syncthreads();
        if (c + 1 < nchunks) cpa_chunk(c + 1, (c + 1) & 1);

        const uint32_t base = sb + (uint32_t)(((c & 1) * GSTAGE) << 2);

        #pragma unroll
        for (int kk = 0; kk < 2; kk++) {
            const int k0 = kk * 8;
            uint32_t aH[2][4], aL[2][4];
            #pragma unroll
            for (int mi = 0; mi < 2; mi++) {
                uint32_t arow = (uint32_t)((wm + mi * 16 + a_row) * GSTR + k0 + a_wof);
                ldsm_x4(aH[mi][0], aH[mi][1], aH[mi][2], aH[mi][3],
                        base + ((0 * GT + arow) << 2));
                ldsm_x4(aL[mi][0], aL[mi][1], aL[mi][2], aL[mi][3],
                        base + ((1 * GT + arow) << 2));
            }
            #pragma unroll
            for (int np = 0; np < 4; np++) {
                uint32_t nrow = (uint32_t)((wn + np * 16 + b_row) * GSTR + k0 + b_wof);
                uint32_t bh[4], bl[4];
                ldsm_x4(bh[0], bh[1], bh[2], bh[3], base + ((2 * GT + nrow) << 2));
                ldsm_x4(bl[0], bl[1], bl[2], bl[3], base + ((3 * GT + nrow) << 2));
                #pragma unroll
                for (int half = 0; half < 2; half++) {
                    const int nf = np * 2 + half;
                    #pragma unroll
                    for (int mi = 0; mi < 2; mi++) {
                        mma_bf16(acc[mi][nf], aH[mi], bh + 2 * half);
                        mma_bf16(acc[mi][nf], aH[mi], bl + 2 * half);
                        mma_bf16(acc[mi][nf], aL[mi], bh + 2 * half);
                    }
                }
            }
        }
    }

    const int nw = N >> 1;
    #pragma unroll
    for (int mi = 0; mi < 2; mi++) {
        const int r0 = brow + wm + mi * 16 + g;
        #pragma unroll
        for (int nf = 0; nf < 8; nf++) {
            const int c0 = bcol + wn + nf * 8 + 2 * t;
            float bx = bias[c0], by = bias[c0 + 1];
            float v0 = acc[mi][nf][0] + bx, v1 = acc[mi][nf][1] + by;
            float v2 = acc[mi][nf][2] + bx, v3 = acc[mi][nf][3] + by;
            if (Cf) {
                *(float2*)(Cf + (size_t)r0 * N + c0)       = make_float2(v0, v1);
                *(float2*)(Cf + (size_t)(r0 + 8) * N + c0) = make_float2(v2, v3);
            } else {
                float sc = (c0 < scaleCols) ? scaleVal : 1.0f;
                v0 *= sc; v1 *= sc; v2 *= sc; v3 *= sc;
                uint32_t h, l;
                bf16x2_split(v0, v1, h, l);
                Ch[(size_t)r0 * nw + (c0 >> 1)] = h;
                Cl[(size_t)r0 * nw + (c0 >> 1)] = l;
                bf16x2_split(v2, v3, h, l);
                Ch[(size_t)(r0 + 8) * nw + (c0 >> 1)] = h;
                Cl[(size_t)(r0 + 8) * nw + (c0 >> 1)] = l;
            }
        }
    }
}

// ===========================================================================
// bf16x3 flash attention, 2 CTAs/SM.
// cp.async staging for Q/K/V (no prefetch regs, no transpose-on-store);
// V kept [key][hd], PV B-fragments via ldmatrix.x4.trans;
// Q fragments reloaded per-tile from smem (not register-resident).
// ===========================================================================
constexpr int QSTR = 36;                     // padded word stride
constexpr int AT_Q  = 128 * QSTR;            // per half (hi or lo)
constexpr int AT_KV = 64 * QSTR;
constexpr int AT_STAGE = 4 * AT_KV;          // KH KL VH VL
constexpr int ATTN_SMEM = (2 * AT_Q + 2 * AT_STAGE) * 4;  // 110,592 B

__global__ __launch_bounds__(256, 2)
void attn_bf16(const uint32_t* __restrict__ Qh, const uint32_t* __restrict__ Ql,
               uint32_t* __restrict__ Oh, uint32_t* __restrict__ Ol)
{
    extern __shared__ uint32_t smw[];
    const uint32_t sb = smem_u32(smw);
    const uint32_t qhb = sb;                               // QH
    const uint32_t qlb = sb + (uint32_t)(AT_Q << 2);       // QL
    const uint32_t stg = qlb + (uint32_t)(AT_Q << 2);      // stages

    const int tid  = threadIdx.x;
    const int w    = tid >> 5;
    const int lane = tid & 31;
    const int g    = lane >> 2;
    const int t    = lane & 3;

    const int lm8 = lane & 7;
    const int lq  = lane >> 3;
    // non-trans (A for QK from Q; B for QK from K rows=keys)
    const int a_row = lm8 + (lq & 1) * 8;
    const int a_wof = (lq >> 1) * 4;
    const int b_row = lm8 + (lq >> 1) * 8;
    const int b_wof = (lq & 1) * 4;
    // trans (B for PV from V rows=keys, cols=hd)
    const int v_row = lm8 + (lq & 1) * 8;
    const int v_wof = (lq >> 1) * 4;

    const int bh = blockIdx.y;
    const int b  = bh >> 4;
    const int h  = bh & 15;
    const int q0 = blockIdx.x * 128;

    const size_t rowbase = (size_t)(b * kS) * kQKVW;
    const int qoff = h * 32;
    const int koff = 512 + h * 32;
    const int voff = 1024 + h * 32;

    // ---- stage Q (hi + lo) via cp.async ----
    {
        #pragma unroll
        for (int i = 0; i < 8; i++) {
            int idx = tid + 256 * i;            // 0..2047
            int arr = idx >> 10;                // 0: hi, 1: lo
            int rem = idx & 1023;
            int r   = rem >> 3;
            int ch  = (rem & 7) * 4;
            const uint32_t* src = (arr ? Ql : Qh) + rowbase
                                + (size_t)(q0 + r) * kQKVW + qoff + ch;
            uint32_t dst = (arr ? qlb : qhb) + (uint32_t)((r * QSTR + ch) << 2);
            cp_async16(dst, src);
        }
        cp_commit();
    }

    float o[8][4];
    #pragma unroll
    for (int nf = 0; nf < 8; nf++)
        #pragma unroll
        for (int e = 0; e < 4; e++) o[nf][e] = 0.f;
    float lsum0 = 0.f, lsum1 = 0.f;

    // ---- cp.async K/V tile staging ----
    auto cpa_tile = [&](int kt, int buf) {
        const uint32_t s = stg + (uint32_t)((buf * AT_STAGE) << 2);
        #pragma unroll
        for (int i = 0; i < 8; i++) {
            int idx = tid + 256 * i;            // 0..2047
            int arr = idx >> 9;                 // 0:KH 1:KL 2:VH 3:VL
            int rem = idx & 511;
            int key = rem >> 3;
            int ch  = (rem & 7) * 4;
            int off = (arr < 2) ? koff : voff;
            const uint32_t* base = ((arr & 1) ? Ql : Qh);
            const uint32_t* src = base + rowbase
                                + (size_t)(kt + key) * kQKVW + off + ch;
            uint32_t dst = s + (uint32_t)((arr * AT_KV + key * QSTR + ch) << 2);
            cp_async16(dst, src);
        }
        cp_commit();
    };

    cpa_tile(0, 0);

    const uint32_t kvb = (uint32_t)(AT_KV << 2);

    for (int tI = 0; tI < kS / 64; tI++) {
        cp_wait0();
        __syncthreads();
        if (tI + 1 < kS / 64) cpa_tile((tI + 1) * 64, (tI + 1) & 1);

        const uint32_t stb = stg + (uint32_t)(((tI & 1) * AT_STAGE) << 2);

        // ---- S = qH kH + qL kH + qH kL ----
        float s[8][4];
        #pragma unroll
        for (int nf = 0; nf < 8; nf++)
            s[nf][0] = s[nf][1] = s[nf][2] = s[nf][3] = 0.f;

        #pragma unroll
        for (int ks = 0; ks < 4; ks++) {
            const int k0 = ks * 8;
            uint32_t qH[4], qL[4];
            uint32_t qrow = (uint32_t)(((w * 16 + a_row) * QSTR + k0 + a_wof) << 2);
            ldsm_x4(qH[0], qH[1], qH[2], qH[3], qhb + qrow);
            ldsm_x4(qL[0], qL[1], qL[2], qL[3], qlb + qrow);
            #pragma unroll
            for (int np = 0; np < 4; np++) {
                uint32_t roff = (uint32_t)(((np * 16 + b_row) * QSTR + k0 + b_wof) << 2);
                uint32_t kh[4], kl[4];
                ldsm_x4(kh[0], kh[1], kh[2], kh[3], stb + roff);
                ldsm_x4(kl[0], kl[1], kl[2], kl[3], stb + kvb + roff);
                #pragma unroll
                for (int half = 0; half < 2; half++) {
                    const int nf = np * 2 + half;
                    mma_bf16(s[nf], qH, kh + 2 * half);
                    mma_bf16(s[nf], qL, kh + 2 * half);
                    mma_bf16(s[nf], qH, kl + 2 * half);
                }
            }
        }

        // ---- exp + row-sum + pack P (hi/lo split) ----
        #pragma unroll
        for (int nf = 0; nf < 8; nf++) {
            float p0 = __expf(s[nf][0]);
            float p1 = __expf(s[nf][1]);
            float p2 = __expf(s[nf][2]);
            float p3 = __expf(s[nf][3]);
            s[nf][0] = p0; s[nf][1] = p1; s[nf][2] = p2; s[nf][3] = p3;
            lsum0 += p0 + p1;
            lsum1 += p2 + p3;
        }
        uint32_t pah[4][4], pal[4][4];
        #pragma unroll
        for (int kc = 0; kc < 4; kc++) {
            bf16x2_split(s[2*kc][0],   s[2*kc][1],   pah[kc][0], pal[kc][0]);
            bf16x2_split(s[2*kc][2],   s[2*kc][3],   pah[kc][1], pal[kc][1]);
            bf16x2_split(s[2*kc+1][0], s[2*kc+1][1], pah[kc][2], pal[kc][2]);
            bf16x2_split(s[2*kc+1][2], s[2*kc+1][3], pah[kc][3], pal[kc][3]);
        }

        // ---- O += pH vH + pL vH + pH vL  (V via trans ldmatrix) ----
        #pragma unroll
        for (int kc = 0; kc < 4; kc++) {
            #pragma unroll
            for (int np = 0; np < 4; np++) {
                // V stored [key][hd-word]; block rows = keys kc*16.., cols = hd np*16..
                uint32_t roff = (uint32_t)(
                    ((kc * 16 + v_row) * QSTR + np * 8 + v_wof) << 2);
                uint32_t vh[4], vl[4];
                ldsm_x4_t(vh[0], vh[1], vh[2], vh[3], stb + 2 * kvb + roff);
                ldsm_x4_t(vl[0], vl[1], vl[2], vl[3], stb + 3 * kvb + roff);
                #pragma unroll
                for (int half = 0; half < 2; half++) {
                    const int nf = np * 2 + half;
                    mma_bf16(o[nf], pah[kc], vh + 2 * half);
                    mma_bf16(o[nf], pal[kc], vh + 2 * half);
                    mma_bf16(o[nf], pah[kc], vl + 2 * half);
                }
            }
        }
    }

    // ---- reduce, normalize, split-pack, store ctx ----
    lsum0 += __shfl_xor_sync(0xFFFFFFFFu, lsum0, 1);
    lsum0 += __shfl_xor_sync(0xFFFFFFFFu, lsum0, 2);
    lsum1 += __shfl_xor_sync(0xFFFFFFFFu, lsum1, 1);
    lsum1 += __shfl_xor_sync(0xFFFFFFFFu, lsum1, 2);
    const float inv0 = 1.f / lsum0;
    const float inv1 = 1.f / lsum1;

    const size_t row0 = (size_t)(b * kS + q0 + w * 16 + g);
    #pragma unroll
    for (int nf = 0; nf < 8; nf++) {
        const int cw = h * 32 + nf * 4 + t;
        uint32_t hw, lw;
        bf16x2_split(o[nf][0] * inv0, o[nf][1] * inv0, hw, lw);
        Oh[row0 * kRW + cw] = hw;
        Ol[row0 * kRW + cw] = lw;
        bf16x2_split(o[nf][2] * inv1, o[nf][3] * inv1, hw, lw);
        Oh[(row0 + 8) * kRW + cw] = hw;
        Ol[(row0 + 8) * kRW + cw] = lw;
    }
}

// ===========================================================================
// launch
// ===========================================================================
extern "C" void kernel_launch(void* const* d_in, const int* in_sizes, int n_in,
                              void* d_out, int out_size)
{
    const float* x  = (const float*)d_in[0];
    const float* Wq = (const float*)d_in[1];
    const float* bq = (const float*)d_in[2];
    const float* Wk = (const float*)d_in[3];
    const float* bk = (const float*)d_in[4];
    const float* Wv = (const float*)d_in[5];
    const float* bv = (const float*)d_in[6];
    const float* Wo = (const float*)d_in[7];
    const float* bo = (const float*)d_in[8];
    float* out = (float*)d_out;

    uint32_t *xs_hi, *xs_lo, *wall_hi, *wall_lo, *wo_hi, *wo_lo;
    uint32_t *qkv_hi, *qkv_lo, *ctx_hi, *ctx_lo;
    float* bias_all;
    cudaGetSymbolAddress((void**)&xs_hi,   g_xs_hi);
    cudaGetSymbolAddress((void**)&xs_lo,   g_xs_lo);
    cudaGetSymbolAddress((void**)&wall_hi, g_wall_hi);
    cudaGetSymbolAddress((void**)&wall_lo, g_wall_lo);
    cudaGetSymbolAddress((void**)&wo_hi,   g_wo_hi);
    cudaGetSymbolAddress((void**)&wo_lo,   g_wo_lo);
    cudaGetSymbolAddress((void**)&bias_all,g_bias_all);
    cudaGetSymbolAddress((void**)&qkv_hi,  g_qkv_hi);
    cudaGetSymbolAddress((void**)&qkv_lo,  g_qkv_lo);
    cudaGetSymbolAddress((void**)&ctx_hi,  g_ctx_hi);
    cudaGetSymbolAddress((void**)&ctx_lo,  g_ctx_lo);

    cudaFuncSetAttribute(gemm_bf16x3,
                         cudaFuncAttributeMaxDynamicSharedMemorySize, GEMM_SMEM);
    cudaFuncSetAttribute(attn_bf16,
                         cudaFuncAttributeMaxDynamicSharedMemorySize, ATTN_SMEM);

    const int wq4 = kHID * kD / 4;   // 262144
    split_kernel<<<kM * kD / 4 / 256, 256>>>(x, xs_hi, xs_lo, kM * kD / 4);
    split_w4_kernel<<<4 * wq4 / 256, 256>>>(Wq, Wk, Wv, Wo,
                                            wall_hi, wall_lo, wo_hi, wo_lo, wq4);
    bias3_kernel<<<12, 256>>>(bq, bk, bv, bias_all);

    // fused QKV projection (3-term): M=4096, N=3072, Q scaled by 1/32
    dim3 gqkv(3 * kHID / 128, kM / 128);   // (24, 32)
    gemm_bf16x3<<<gqkv, 256, GEMM_SMEM>>>(
        xs_hi, xs_lo, wall_hi, wall_lo, bias_all,
        nullptr, qkv_hi, qkv_lo, kM, 3 * kHID, kD, kHID, kScale);

    dim3 ga(kS / 128, kB * kH);            // (16, 32)
    attn_bf16<<<ga, 256, ATTN_SMEM>>>(qkv_hi, qkv_lo, ctx_hi, ctx_lo);

    // output projection (3-term)
    dim3 go(kD / 128, kM / 128);           // (8, 32)
    gemm_bf16x3<<<go, 256, GEMM_SMEM>>>(
        ctx_hi, ctx_lo, wo_hi, wo_lo, bo,
        out, nullptr, nullptr, kM, kD, kHID, 0, 1.0f);
}